// round 1
// baseline (speedup 1.0000x reference)
#include <cuda_runtime.h>
#include <float.h>

#define DIMX 1024
#define NH 16
#define HD 64
#define QL 1024
#define KL 4096
#define BS 2

// Scratch (allocation-free rule: __device__ globals)
__device__ float g_Qp[BS * QL * DIMX];   // Q projection (pre-scaled by 1/8)
__device__ float g_Kp[BS * KL * DIMX];   // K projection
__device__ float g_Vp[BS * KL * DIMX];   // V projection
__device__ float g_Ao[BS * QL * DIMX];   // attention output (pre-Wo)

// ---------------------------------------------------------------------------
// C[M,1024] = (A[M,1024] @ W[1024,1024]^T + bias[1024]) * scale
// 64x64 tile, BK=16, 4x4 register tile per thread, 256 threads.
// ---------------------------------------------------------------------------
__global__ __launch_bounds__(256) void gemm_nt(const float* __restrict__ A,
                                               const float* __restrict__ W,
                                               const float* __restrict__ bias,
                                               float* __restrict__ C,
                                               float scale) {
    __shared__ __align__(16) float As[16][68];
    __shared__ __align__(16) float Bs[16][68];
    const int K = DIMX, N = DIMX;
    const int tid = threadIdx.x;
    const int tx = tid & 15, ty = tid >> 4;
    const int m0 = blockIdx.y * 64, n0 = blockIdx.x * 64;
    const int lr = tid >> 2;          // row within tile (0..63)
    const int lc = (tid & 3) * 4;     // k-col within tile (0,4,8,12)

    const float* Ag = A + (size_t)(m0 + lr) * K + lc;
    const float* Wg = W + (size_t)(n0 + lr) * K + lc;

    float acc[4][4] = {};

    for (int k0 = 0; k0 < K; k0 += 16) {
        float4 a = *reinterpret_cast<const float4*>(Ag + k0);
        float4 b = *reinterpret_cast<const float4*>(Wg + k0);
        As[lc + 0][lr] = a.x; As[lc + 1][lr] = a.y;
        As[lc + 2][lr] = a.z; As[lc + 3][lr] = a.w;
        Bs[lc + 0][lr] = b.x; Bs[lc + 1][lr] = b.y;
        Bs[lc + 2][lr] = b.z; Bs[lc + 3][lr] = b.w;
        __syncthreads();
#pragma unroll
        for (int kk = 0; kk < 16; kk++) {
            float4 ra = *reinterpret_cast<const float4*>(&As[kk][ty * 4]);
            float4 rb = *reinterpret_cast<const float4*>(&Bs[kk][tx * 4]);
            float ar[4] = {ra.x, ra.y, ra.z, ra.w};
            float br[4] = {rb.x, rb.y, rb.z, rb.w};
#pragma unroll
            for (int i = 0; i < 4; i++)
#pragma unroll
                for (int j = 0; j < 4; j++) acc[i][j] += ar[i] * br[j];
        }
        __syncthreads();
    }

#pragma unroll
    for (int i = 0; i < 4; i++) {
        int m = m0 + ty * 4 + i;
#pragma unroll
        for (int j = 0; j < 4; j++) {
            int n = n0 + tx * 4 + j;
            C[(size_t)m * N + n] = (acc[i][j] + bias[n]) * scale;
        }
    }
}

// ---------------------------------------------------------------------------
// Flash-style masked attention over projected Q/K/V.
// Block: 64 q-rows of one (batch, head). Loops k in 64-row tiles.
// grid = (QL/64, NH, BS), 256 threads, dynamic smem.
// Mask semantics match reference exactly: masked score = -FLT_MAX
// (finfo(float32).min); fully masked rows -> uniform 1/KL weights.
// ---------------------------------------------------------------------------
__global__ __launch_bounds__(256) void attn_kernel(const int* __restrict__ q_m,
                                                   const int* __restrict__ k_m) {
    extern __shared__ __align__(16) float sm[];
    float* Qs = sm;               // [d][q]  : Qs[d*64 + q]
    float* Ks = Qs + 64 * 64;     // [d][k]  : Ks[d*64 + k]
    float* Vs = Ks + 64 * 64;     // [k][d]  : Vs[k*64 + d]
    float* Ps = Vs + 64 * 64;     // [q][k]  : Ps[q*68 + k] (padded stride)
    __shared__ int qm_s[64];
    __shared__ int km_s[64];

    const int tid = threadIdx.x;
    const int tx = tid & 15, ty = tid >> 4;
    const int q0 = blockIdx.x * 64;
    const int h = blockIdx.y;
    const int b = blockIdx.z;

    // --- load Q tile (transposed into [d][q]) + q mask ---
    const float* Qg = g_Qp + ((size_t)(b * QL + q0)) * DIMX + h * HD;
#pragma unroll
    for (int r = 0; r < 4; r++) {
        int row = (tid >> 4) + r * 16;   // q index within tile
        int c = (tid & 15) * 4;          // d index
        float4 v = *reinterpret_cast<const float4*>(Qg + (size_t)row * DIMX + c);
        Qs[(c + 0) * 64 + row] = v.x; Qs[(c + 1) * 64 + row] = v.y;
        Qs[(c + 2) * 64 + row] = v.z; Qs[(c + 3) * 64 + row] = v.w;
    }
    if (tid < 64) qm_s[tid] = q_m[b * QL + q0 + tid];

    float m_i[4], l_i[4], acc[4][4] = {};
#pragma unroll
    for (int i = 0; i < 4; i++) { m_i[i] = -FLT_MAX; l_i[i] = 0.0f; }

    const float* Kg = g_Kp + ((size_t)(b * KL)) * DIMX + h * HD;
    const float* Vg = g_Vp + ((size_t)(b * KL)) * DIMX + h * HD;

    for (int kt = 0; kt < KL / 64; kt++) {
        const int k0 = kt * 64;
        __syncthreads();   // prior-iteration reads of Ks/Vs/Ps done
        // --- load K (transposed [d][k]) and V ([k][d]) tiles + k mask ---
#pragma unroll
        for (int r = 0; r < 4; r++) {
            int row = (tid >> 4) + r * 16;   // k index within tile
            int c = (tid & 15) * 4;          // d index
            float4 kv = *reinterpret_cast<const float4*>(Kg + (size_t)(k0 + row) * DIMX + c);
            Ks[(c + 0) * 64 + row] = kv.x; Ks[(c + 1) * 64 + row] = kv.y;
            Ks[(c + 2) * 64 + row] = kv.z; Ks[(c + 3) * 64 + row] = kv.w;
            float4 vv = *reinterpret_cast<const float4*>(Vg + (size_t)(k0 + row) * DIMX + c);
            *reinterpret_cast<float4*>(&Vs[row * 64 + c]) = vv;
        }
        if (tid < 64) km_s[tid] = k_m[b * KL + k0 + tid];
        __syncthreads();

        // --- S = Q K^T (64x64x64) ---
        float s[4][4] = {};
#pragma unroll
        for (int d = 0; d < 64; d++) {
            float4 ra = *reinterpret_cast<const float4*>(&Qs[d * 64 + ty * 4]);
            float4 rb = *reinterpret_cast<const float4*>(&Ks[d * 64 + tx * 4]);
            float ar[4] = {ra.x, ra.y, ra.z, ra.w};
            float br[4] = {rb.x, rb.y, rb.z, rb.w};
#pragma unroll
            for (int i = 0; i < 4; i++)
#pragma unroll
                for (int j = 0; j < 4; j++) s[i][j] += ar[i] * br[j];
        }

        // --- mask + online softmax update ---
        int qmv[4], kmv[4];
#pragma unroll
        for (int i = 0; i < 4; i++) qmv[i] = qm_s[ty * 4 + i];
#pragma unroll
        for (int j = 0; j < 4; j++) kmv[j] = km_s[tx * 4 + j];

        float alpha[4];
#pragma unroll
        for (int i = 0; i < 4; i++) {
            float rm = -FLT_MAX;
#pragma unroll
            for (int j = 0; j < 4; j++) {
                float sv = (qmv[i] != 0 && kmv[j] != 0) ? s[i][j] : -FLT_MAX;
                s[i][j] = sv;
                rm = fmaxf(rm, sv);
            }
#pragma unroll
            for (int off = 8; off > 0; off >>= 1)
                rm = fmaxf(rm, __shfl_xor_sync(0xffffffffu, rm, off));
            float nm = fmaxf(m_i[i], rm);
            alpha[i] = expf(m_i[i] - nm);     // (-FLT_MAX)-(-FLT_MAX)=0 -> 1
            float rs = 0.0f;
#pragma unroll
            for (int j = 0; j < 4; j++) {
                float p = expf(s[i][j] - nm); // masked & nm finite -> 0; all-masked -> 1
                s[i][j] = p;
                rs += p;
            }
#pragma unroll
            for (int off = 8; off > 0; off >>= 1)
                rs += __shfl_xor_sync(0xffffffffu, rs, off);
            l_i[i] = l_i[i] * alpha[i] + rs;
            m_i[i] = nm;
        }

        // --- stage P to smem, rescale O accumulator ---
#pragma unroll
        for (int i = 0; i < 4; i++)
#pragma unroll
            for (int j = 0; j < 4; j++)
                Ps[(ty * 4 + i) * 68 + tx * 4 + j] = s[i][j];
#pragma unroll
        for (int i = 0; i < 4; i++)
#pragma unroll
            for (int j = 0; j < 4; j++) acc[i][j] *= alpha[i];
        __syncthreads();

        // --- O += P V (64x64x64, contraction over k) ---
#pragma unroll 8
        for (int kk = 0; kk < 64; kk++) {
            float4 v = *reinterpret_cast<const float4*>(&Vs[kk * 64 + tx * 4]);
            float vr[4] = {v.x, v.y, v.z, v.w};
#pragma unroll
            for (int i = 0; i < 4; i++) {
                float pi = Ps[(ty * 4 + i) * 68 + kk];
#pragma unroll
                for (int j = 0; j < 4; j++) acc[i][j] += pi * vr[j];
            }
        }
    }

    // --- normalize and write [bs, q_len, dim] layout ---
#pragma unroll
    for (int i = 0; i < 4; i++) {
        float inv = 1.0f / l_i[i];
        size_t row = (size_t)(b * QL + q0 + ty * 4 + i) * DIMX + h * HD;
#pragma unroll
        for (int j = 0; j < 4; j++)
            g_Ao[row + tx * 4 + j] = acc[i][j] * inv;
    }
}

// ---------------------------------------------------------------------------
extern "C" void kernel_launch(void* const* d_in, const int* in_sizes, int n_in,
                              void* d_out, int out_size) {
    // Resolve q / k / q_m / k_m among the first four inputs by element count
    // (metadata order could be dict order or signature order; sizes are unique).
    const float* q = nullptr;
    const float* k = nullptr;
    const int* qm = nullptr;
    const int* km = nullptr;
    for (int i = 0; i < 4; i++) {
        int s = in_sizes[i];
        if (s == BS * QL * DIMX)      q  = (const float*)d_in[i];
        else if (s == BS * KL * DIMX) k  = (const float*)d_in[i];
        else if (s == BS * QL)        qm = (const int*)d_in[i];
        else if (s == BS * KL)        km = (const int*)d_in[i];
    }
    const float* Wq = (const float*)d_in[4];
    const float* bq = (const float*)d_in[5];
    const float* Wk = (const float*)d_in[6];
    const float* bk = (const float*)d_in[7];
    const float* Wv = (const float*)d_in[8];
    const float* bv = (const float*)d_in[9];
    const float* Wo = (const float*)d_in[10];
    const float* bo = (const float*)d_in[11];
    float* out = (float*)d_out;

    float* Qp; cudaGetSymbolAddress((void**)&Qp, g_Qp);
    float* Kp; cudaGetSymbolAddress((void**)&Kp, g_Kp);
    float* Vp; cudaGetSymbolAddress((void**)&Vp, g_Vp);
    float* Ao; cudaGetSymbolAddress((void**)&Ao, g_Ao);

    const int smem_attn = (3 * 64 * 64 + 64 * 68) * (int)sizeof(float);
    cudaFuncSetAttribute(attn_kernel, cudaFuncAttributeMaxDynamicSharedMemorySize,
                         smem_attn);

    dim3 blk(256);
    // Q projection (scaled by 1/sqrt(64))
    gemm_nt<<<dim3(DIMX / 64, BS * QL / 64), blk>>>(q, Wq, bq, Qp, 0.125f);
    // K projection
    gemm_nt<<<dim3(DIMX / 64, BS * KL / 64), blk>>>(k, Wk, bk, Kp, 1.0f);
    // V projection (input is k)
    gemm_nt<<<dim3(DIMX / 64, BS * KL / 64), blk>>>(k, Wv, bv, Vp, 1.0f);
    // attention
    attn_kernel<<<dim3(QL / 64, NH, BS), blk, smem_attn>>>(qm, km);
    // output projection
    gemm_nt<<<dim3(DIMX / 64, BS * QL / 64), blk>>>(Ao, Wo, bo, out, 1.0f);
}

// round 3
// speedup vs baseline: 1.3897x; 1.3897x over previous
#include <cuda_runtime.h>
#include <cuda_bf16.h>
#include <float.h>
#include <stdint.h>

#define DIMX 1024
#define NH 16
#define HD 64
#define QL 1024
#define KL 4096
#define BS 2

#define KP 3072            // packed K' = 3 * 1024 (bf16 split: hh + hl + lh)
#define BM 128
#define BN 128
#define BK 32
#define NKT (KP / BK)      // 96 k-tiles
#define ASTR 40            // smem row stride in bf16 (80 bytes -> ldmatrix conflict-free)

// ---------------- scratch (__device__ globals; no allocation) ----------------
__device__ float g_Qp[BS * QL * DIMX];
__device__ float g_Kp[BS * KL * DIMX];
__device__ float g_Vp[BS * KL * DIMX];
__device__ float g_Ao[BS * QL * DIMX];

__device__ __nv_bfloat16 g_q2[BS * QL * KP];
__device__ __nv_bfloat16 g_k2[BS * KL * KP];
__device__ __nv_bfloat16 g_o2[BS * QL * KP];
__device__ __nv_bfloat16 g_Wq2[DIMX * KP];
__device__ __nv_bfloat16 g_Wk2[DIMX * KP];
__device__ __nv_bfloat16 g_Wv2[DIMX * KP];
__device__ __nv_bfloat16 g_Wo2[DIMX * KP];

// ---------------- low-level helpers (baseline PTX only: sm_80-era) -----------
__device__ __forceinline__ uint32_t smem_u32(const void* p) {
    uint32_t a;
    asm("{ .reg .u64 t; cvta.to.shared.u64 t, %1; cvt.u32.u64 %0, t; }" : "=r"(a) : "l"(p));
    return a;
}
#define CP_ASYNC16(dst, src) \
    asm volatile("cp.async.cg.shared.global [%0], [%1], 16;" :: "r"(dst), "l"(src))
#define CP_COMMIT() asm volatile("cp.async.commit_group;" ::: "memory")
#define CP_WAIT(n)  asm volatile("cp.async.wait_group %0;" :: "n"(n) : "memory")

__device__ __forceinline__ void ldsm_x4(uint32_t& r0, uint32_t& r1, uint32_t& r2,
                                        uint32_t& r3, uint32_t addr) {
    asm volatile("ldmatrix.sync.aligned.m8n8.x4.shared.b16 {%0,%1,%2,%3}, [%4];"
                 : "=r"(r0), "=r"(r1), "=r"(r2), "=r"(r3) : "r"(addr));
}
__device__ __forceinline__ void mma_bf16(float* c, const uint32_t* a, const uint32_t* b) {
    asm volatile(
        "mma.sync.aligned.m16n8k16.row.col.f32.bf16.bf16.f32 "
        "{%0,%1,%2,%3}, {%4,%5,%6,%7}, {%8,%9}, {%0,%1,%2,%3};"
        : "+f"(c[0]), "+f"(c[1]), "+f"(c[2]), "+f"(c[3])
        : "r"(a[0]), "r"(a[1]), "r"(a[2]), "r"(a[3]), "r"(b[0]), "r"(b[1]));
}

// ---------------- fp32 -> (bf16 hi, lo) pack kernels ----------------
// A layout over K'=3072: [hi | hi | lo];  B layout: [hi | lo | hi]
__global__ __launch_bounds__(256) void pack_a(const float* __restrict__ x,
                                              __nv_bfloat16* __restrict__ y) {
    int idx = blockIdx.x * 256 + threadIdx.x;
    int m = idx >> 9;
    int j = (idx & 511) * 2;
    float2 v = *reinterpret_cast<const float2*>(x + (size_t)m * DIMX + j);
    __nv_bfloat16 h0 = __float2bfloat16(v.x), h1 = __float2bfloat16(v.y);
    __nv_bfloat16 l0 = __float2bfloat16(v.x - __bfloat162float(h0));
    __nv_bfloat16 l1 = __float2bfloat16(v.y - __bfloat162float(h1));
    __nv_bfloat162 h; h.x = h0; h.y = h1;
    __nv_bfloat162 l; l.x = l0; l.y = l1;
    size_t base = (size_t)m * KP;
    *reinterpret_cast<__nv_bfloat162*>(y + base + j) = h;
    *reinterpret_cast<__nv_bfloat162*>(y + base + DIMX + j) = h;
    *reinterpret_cast<__nv_bfloat162*>(y + base + 2 * DIMX + j) = l;
}
__global__ __launch_bounds__(256) void pack_b(const float* __restrict__ x,
                                              __nv_bfloat16* __restrict__ y) {
    int idx = blockIdx.x * 256 + threadIdx.x;
    int m = idx >> 9;
    int j = (idx & 511) * 2;
    float2 v = *reinterpret_cast<const float2*>(x + (size_t)m * DIMX + j);
    __nv_bfloat16 h0 = __float2bfloat16(v.x), h1 = __float2bfloat16(v.y);
    __nv_bfloat16 l0 = __float2bfloat16(v.x - __bfloat162float(h0));
    __nv_bfloat16 l1 = __float2bfloat16(v.y - __bfloat162float(h1));
    __nv_bfloat162 h; h.x = h0; h.y = h1;
    __nv_bfloat162 l; l.x = l0; l.y = l1;
    size_t base = (size_t)m * KP;
    *reinterpret_cast<__nv_bfloat162*>(y + base + j) = h;
    *reinterpret_cast<__nv_bfloat162*>(y + base + DIMX + j) = l;
    *reinterpret_cast<__nv_bfloat162*>(y + base + 2 * DIMX + j) = h;
}

// ---------------- warp-MMA GEMM: C[M,1024] = (A2 @ B2^T + bias) * scale -----
// A2: [M][KP] bf16 row-major, B2: [1024][KP] bf16 row-major (so B2^T is col-major
// k x n == "col" operand of mma.sync row.col). 128x128 tile, BK=32, 8 warps of
// 32x64, cp.async double-buffered smem with 80B-padded rows.
__global__ __launch_bounds__(256) void gemm_mma(const __nv_bfloat16* __restrict__ A,
                                                const __nv_bfloat16* __restrict__ B,
                                                const float* __restrict__ bias,
                                                float* __restrict__ C, float scale) {
    __shared__ __align__(16) __nv_bfloat16 sh[2 * 2 * BM * ASTR];
    const uint32_t sbase = smem_u32(sh);
    // stage s: A at sbase + s*20480, B at +10240 (bytes)
    const int tid = threadIdx.x;
    const int lane = tid & 31;
    const int wid = tid >> 5;
    const int wm = (wid & 3) * 32;      // warp row offset in tile
    const int wn = (wid >> 2) * 64;     // warp col offset in tile
    const int n0 = blockIdx.x * BN, m0 = blockIdx.y * BM;

    const __nv_bfloat16* Abase = A + (size_t)m0 * KP;
    const __nv_bfloat16* Bbase = B + (size_t)n0 * KP;

    // per-thread load chunks: c = tid, tid+256; row = c>>2, seg = c&3 (16B segs)
    const int r0_ = tid >> 2, r1_ = (tid + 256) >> 2;
    const int s0_ = (tid & 3) * 8, s1_ = s0_;  // seg*8 bf16 elements
    const uint32_t soffA0 = (uint32_t)(r0_ * 80 + (tid & 3) * 16);
    const uint32_t soffA1 = (uint32_t)(r1_ * 80 + (tid & 3) * 16);

    float acc[2][8][4] = {};

    auto load_stage = [&](int kt, int s) {
        uint32_t sa = sbase + (uint32_t)s * 20480u;
        uint32_t sb = sa + 10240u;
        const __nv_bfloat16* Ak = Abase + kt * BK;
        const __nv_bfloat16* Bk = Bbase + kt * BK;
        CP_ASYNC16(sa + soffA0, Ak + (size_t)r0_ * KP + s0_);
        CP_ASYNC16(sa + soffA1, Ak + (size_t)r1_ * KP + s1_);
        CP_ASYNC16(sb + soffA0, Bk + (size_t)r0_ * KP + s0_);
        CP_ASYNC16(sb + soffA1, Bk + (size_t)r1_ * KP + s1_);
        CP_COMMIT();
    };

    load_stage(0, 0);

    for (int kt = 0; kt < NKT; kt++) {
        if (kt + 1 < NKT) {
            load_stage(kt + 1, (kt + 1) & 1);
            CP_WAIT(1);
        } else {
            CP_WAIT(0);
        }
        __syncthreads();

        uint32_t sa = sbase + (uint32_t)(kt & 1) * 20480u;
        uint32_t sb = sa + 10240u;
#pragma unroll
        for (int s = 0; s < 2; s++) {  // two k16 steps within BK=32
            uint32_t aF[2][4], bF[8][2];
            // A fragments: rows wm + mf*16 + (lane&15), k-half (lane>>4)
#pragma unroll
            for (int mf = 0; mf < 2; mf++) {
                uint32_t addr = sa + (uint32_t)((wm + mf * 16 + (lane & 15)) * 80 +
                                                s * 32 + (lane >> 4) * 16);
                ldsm_x4(aF[mf][0], aF[mf][1], aF[mf][2], aF[mf][3], addr);
            }
            // B fragments: 4 x ldmatrix.x4, each covers 16 n-rows (2 n8-frags)
#pragma unroll
            for (int nf4 = 0; nf4 < 4; nf4++) {
                int nrow = wn + nf4 * 16 + ((lane >> 4) * 8) + (lane & 7);
                uint32_t addr = sb + (uint32_t)(nrow * 80 + s * 32 +
                                                (((lane >> 3) & 1) * 16));
                uint32_t q0, q1, q2, q3;
                ldsm_x4(q0, q1, q2, q3, addr);
                bF[nf4 * 2 + 0][0] = q0; bF[nf4 * 2 + 0][1] = q1;
                bF[nf4 * 2 + 1][0] = q2; bF[nf4 * 2 + 1][1] = q3;
            }
#pragma unroll
            for (int mf = 0; mf < 2; mf++)
#pragma unroll
                for (int nf = 0; nf < 8; nf++)
                    mma_bf16(acc[mf][nf], aF[mf], bF[nf]);
        }
        __syncthreads();
    }

    // -------- epilogue: (acc + bias) * scale -> C --------
#pragma unroll
    for (int mf = 0; mf < 2; mf++) {
        int rbase = m0 + wm + mf * 16 + (lane >> 2);
#pragma unroll
        for (int nf = 0; nf < 8; nf++) {
            int col = n0 + wn + nf * 8 + (lane & 3) * 2;
            float2 bv = *reinterpret_cast<const float2*>(bias + col);
            float2 o0, o1;
            o0.x = (acc[mf][nf][0] + bv.x) * scale;
            o0.y = (acc[mf][nf][1] + bv.y) * scale;
            o1.x = (acc[mf][nf][2] + bv.x) * scale;
            o1.y = (acc[mf][nf][3] + bv.y) * scale;
            *reinterpret_cast<float2*>(C + (size_t)rbase * DIMX + col) = o0;
            *reinterpret_cast<float2*>(C + (size_t)(rbase + 8) * DIMX + col) = o1;
        }
    }
}

// ---------------- flash attention (fp32, __expf) ----------
__global__ __launch_bounds__(256) void attn_kernel(const int* __restrict__ q_m,
                                                   const int* __restrict__ k_m) {
    extern __shared__ __align__(16) float sm[];
    float* Qs = sm;
    float* Ks = Qs + 64 * 64;
    float* Vs = Ks + 64 * 64;
    float* Ps = Vs + 64 * 64;
    __shared__ int qm_s[64];
    __shared__ int km_s[64];

    const int tid = threadIdx.x;
    const int tx = tid & 15, ty = tid >> 4;
    const int q0 = blockIdx.x * 64;
    const int h = blockIdx.y;
    const int b = blockIdx.z;

    const float* Qg = g_Qp + ((size_t)(b * QL + q0)) * DIMX + h * HD;
#pragma unroll
    for (int r = 0; r < 4; r++) {
        int row = (tid >> 4) + r * 16;
        int c = (tid & 15) * 4;
        float4 v = *reinterpret_cast<const float4*>(Qg + (size_t)row * DIMX + c);
        Qs[(c + 0) * 64 + row] = v.x; Qs[(c + 1) * 64 + row] = v.y;
        Qs[(c + 2) * 64 + row] = v.z; Qs[(c + 3) * 64 + row] = v.w;
    }
    if (tid < 64) qm_s[tid] = q_m[b * QL + q0 + tid];

    float m_i[4], l_i[4], acc[4][4] = {};
#pragma unroll
    for (int i = 0; i < 4; i++) { m_i[i] = -FLT_MAX; l_i[i] = 0.0f; }

    const float* Kg = g_Kp + ((size_t)(b * KL)) * DIMX + h * HD;
    const float* Vg = g_Vp + ((size_t)(b * KL)) * DIMX + h * HD;

    for (int kt = 0; kt < KL / 64; kt++) {
        const int k0 = kt * 64;
        __syncthreads();
#pragma unroll
        for (int r = 0; r < 4; r++) {
            int row = (tid >> 4) + r * 16;
            int c = (tid & 15) * 4;
            float4 kv = *reinterpret_cast<const float4*>(Kg + (size_t)(k0 + row) * DIMX + c);
            Ks[(c + 0) * 64 + row] = kv.x; Ks[(c + 1) * 64 + row] = kv.y;
            Ks[(c + 2) * 64 + row] = kv.z; Ks[(c + 3) * 64 + row] = kv.w;
            float4 vv = *reinterpret_cast<const float4*>(Vg + (size_t)(k0 + row) * DIMX + c);
            *reinterpret_cast<float4*>(&Vs[row * 64 + c]) = vv;
        }
        if (tid < 64) km_s[tid] = k_m[b * KL + k0 + tid];
        __syncthreads();

        float s[4][4] = {};
#pragma unroll
        for (int d = 0; d < 64; d++) {
            float4 ra = *reinterpret_cast<const float4*>(&Qs[d * 64 + ty * 4]);
            float4 rb = *reinterpret_cast<const float4*>(&Ks[d * 64 + tx * 4]);
            float ar[4] = {ra.x, ra.y, ra.z, ra.w};
            float br[4] = {rb.x, rb.y, rb.z, rb.w};
#pragma unroll
            for (int i = 0; i < 4; i++)
#pragma unroll
                for (int j = 0; j < 4; j++) s[i][j] += ar[i] * br[j];
        }

        int qmv[4], kmv[4];
#pragma unroll
        for (int i = 0; i < 4; i++) qmv[i] = qm_s[ty * 4 + i];
#pragma unroll
        for (int j = 0; j < 4; j++) kmv[j] = km_s[tx * 4 + j];

        float alpha[4];
#pragma unroll
        for (int i = 0; i < 4; i++) {
            float rm = -FLT_MAX;
#pragma unroll
            for (int j = 0; j < 4; j++) {
                float sv = (qmv[i] != 0 && kmv[j] != 0) ? s[i][j] : -FLT_MAX;
                s[i][j] = sv;
                rm = fmaxf(rm, sv);
            }
#pragma unroll
            for (int off = 8; off > 0; off >>= 1)
                rm = fmaxf(rm, __shfl_xor_sync(0xffffffffu, rm, off));
            float nm = fmaxf(m_i[i], rm);
            alpha[i] = __expf(m_i[i] - nm);
            float rs = 0.0f;
#pragma unroll
            for (int j = 0; j < 4; j++) {
                float p = __expf(s[i][j] - nm);
                s[i][j] = p;
                rs += p;
            }
#pragma unroll
            for (int off = 8; off > 0; off >>= 1)
                rs += __shfl_xor_sync(0xffffffffu, rs, off);
            l_i[i] = l_i[i] * alpha[i] + rs;
            m_i[i] = nm;
        }

#pragma unroll
        for (int i = 0; i < 4; i++)
#pragma unroll
            for (int j = 0; j < 4; j++)
                Ps[(ty * 4 + i) * 68 + tx * 4 + j] = s[i][j];
#pragma unroll
        for (int i = 0; i < 4; i++)
#pragma unroll
            for (int j = 0; j < 4; j++) acc[i][j] *= alpha[i];
        __syncthreads();

#pragma unroll 8
        for (int kk = 0; kk < 64; kk++) {
            float4 v = *reinterpret_cast<const float4*>(&Vs[kk * 64 + tx * 4]);
            float vr[4] = {v.x, v.y, v.z, v.w};
#pragma unroll
            for (int i = 0; i < 4; i++) {
                float pi = Ps[(ty * 4 + i) * 68 + kk];
#pragma unroll
                for (int j = 0; j < 4; j++) acc[i][j] += pi * vr[j];
            }
        }
    }

#pragma unroll
    for (int i = 0; i < 4; i++) {
        float inv = 1.0f / l_i[i];
        size_t row = (size_t)(b * QL + q0 + ty * 4 + i) * DIMX + h * HD;
#pragma unroll
        for (int j = 0; j < 4; j++)
            g_Ao[row + tx * 4 + j] = acc[i][j] * inv;
    }
}

// ---------------- host side ----------------
extern "C" void kernel_launch(void* const* d_in, const int* in_sizes, int n_in,
                              void* d_out, int out_size) {
    const float* q = nullptr;
    const float* k = nullptr;
    const int* qm = nullptr;
    const int* km = nullptr;
    for (int i = 0; i < 4; i++) {
        int s = in_sizes[i];
        if (s == BS * QL * DIMX)      q  = (const float*)d_in[i];
        else if (s == BS * KL * DIMX) k  = (const float*)d_in[i];
        else if (s == BS * QL)        qm = (const int*)d_in[i];
        else if (s == BS * KL)        km = (const int*)d_in[i];
    }
    const float* Wq = (const float*)d_in[4];
    const float* bq = (const float*)d_in[5];
    const float* Wk = (const float*)d_in[6];
    const float* bk = (const float*)d_in[7];
    const float* Wv = (const float*)d_in[8];
    const float* bv = (const float*)d_in[9];
    const float* Wo = (const float*)d_in[10];
    const float* bo = (const float*)d_in[11];
    float* out = (float*)d_out;

    float *Qp, *Kp, *Vp, *Ao;
    cudaGetSymbolAddress((void**)&Qp, g_Qp);
    cudaGetSymbolAddress((void**)&Kp, g_Kp);
    cudaGetSymbolAddress((void**)&Vp, g_Vp);
    cudaGetSymbolAddress((void**)&Ao, g_Ao);
    __nv_bfloat16 *q2, *k2, *o2, *wq2, *wk2, *wv2, *wo2;
    cudaGetSymbolAddress((void**)&q2, g_q2);
    cudaGetSymbolAddress((void**)&k2, g_k2);
    cudaGetSymbolAddress((void**)&o2, g_o2);
    cudaGetSymbolAddress((void**)&wq2, g_Wq2);
    cudaGetSymbolAddress((void**)&wk2, g_Wk2);
    cudaGetSymbolAddress((void**)&wv2, g_Wv2);
    cudaGetSymbolAddress((void**)&wo2, g_Wo2);

    const int smem_attn = (3 * 64 * 64 + 64 * 68) * (int)sizeof(float);
    cudaFuncSetAttribute(attn_kernel, cudaFuncAttributeMaxDynamicSharedMemorySize, smem_attn);

    // ---- pack weights + activations to split-bf16 ----
    pack_b<<<DIMX * DIMX / 512, 256>>>(Wq, wq2);
    pack_b<<<DIMX * DIMX / 512, 256>>>(Wk, wk2);
    pack_b<<<DIMX * DIMX / 512, 256>>>(Wv, wv2);
    pack_b<<<DIMX * DIMX / 512, 256>>>(Wo, wo2);
    pack_a<<<BS * QL * DIMX / 512, 256>>>(q, q2);
    pack_a<<<BS * KL * DIMX / 512, 256>>>(k, k2);

    // ---- projections on tensor cores (mma.sync) ----
    gemm_mma<<<dim3(DIMX / BN, BS * QL / BM), 256>>>(q2, wq2, bq, Qp, 0.125f);
    gemm_mma<<<dim3(DIMX / BN, BS * KL / BM), 256>>>(k2, wk2, bk, Kp, 1.0f);
    gemm_mma<<<dim3(DIMX / BN, BS * KL / BM), 256>>>(k2, wv2, bv, Vp, 1.0f);

    // ---- attention ----
    attn_kernel<<<dim3(QL / 64, NH, BS), 256, smem_attn>>>(qm, km);

    // ---- output projection ----
    pack_a<<<BS * QL * DIMX / 512, 256>>>(Ao, o2);
    gemm_mma<<<dim3(DIMX / BN, BS * QL / BM), 256>>>(o2, wo2, bo, out, 1.0f);
}

// round 4
// speedup vs baseline: 2.7374x; 1.9697x over previous
#include <cuda_runtime.h>
#include <cuda_bf16.h>
#include <float.h>
#include <stdint.h>

#define DIMX 1024
#define NH 16
#define HD 64
#define QL 1024
#define KL 4096
#define BS 2

#define KP 3072            // packed K' = 3 * 1024 (bf16 split: hh + hl + lh)
#define BM 128
#define BN 128
#define BK 32
#define NKT (KP / BK)      // 96 k-tiles
#define GSTG 4             // gemm pipeline stages

// attention tiling
#define BQ 128
#define BKT 128
#define NT (KL / BKT)      // 32 k-tiles
#define SSTR 72            // bf16 elements per smem row (144B)

// ---------------- scratch (__device__ globals; no allocation) ----------------
__device__ __nv_bfloat16 g_q2[BS * QL * KP];
__device__ __nv_bfloat16 g_k2[BS * KL * KP];
__device__ __nv_bfloat16 g_o2[BS * QL * KP];
__device__ __nv_bfloat16 g_Wq2[DIMX * KP];
__device__ __nv_bfloat16 g_Wk2[DIMX * KP];
__device__ __nv_bfloat16 g_Wv2[DIMX * KP];
__device__ __nv_bfloat16 g_Wo2[DIMX * KP];

// projection outputs as split-bf16 planes [rows][1024]
__device__ __nv_bfloat16 g_Qh[BS * QL * DIMX];
__device__ __nv_bfloat16 g_Ql[BS * QL * DIMX];
__device__ __nv_bfloat16 g_Kh[BS * KL * DIMX];
__device__ __nv_bfloat16 g_Kl[BS * KL * DIMX];
__device__ __nv_bfloat16 g_Vh[BS * KL * DIMX];
__device__ __nv_bfloat16 g_Vl[BS * KL * DIMX];

// ---------------- low-level helpers (baseline sm_80-era PTX only) ------------
__device__ __forceinline__ uint32_t smem_u32(const void* p) {
    uint32_t a;
    asm("{ .reg .u64 t; cvta.to.shared.u64 t, %1; cvt.u32.u64 %0, t; }" : "=r"(a) : "l"(p));
    return a;
}
#define CP_ASYNC16(dst, src) \
    asm volatile("cp.async.cg.shared.global [%0], [%1], 16;" :: "r"(dst), "l"(src))
#define CP_COMMIT() asm volatile("cp.async.commit_group;" ::: "memory")
#define CP_WAIT(n)  asm volatile("cp.async.wait_group %0;" :: "n"(n) : "memory")

__device__ __forceinline__ void ldsm_x4(uint32_t& r0, uint32_t& r1, uint32_t& r2,
                                        uint32_t& r3, uint32_t addr) {
    asm volatile("ldmatrix.sync.aligned.m8n8.x4.shared.b16 {%0,%1,%2,%3}, [%4];"
                 : "=r"(r0), "=r"(r1), "=r"(r2), "=r"(r3) : "r"(addr));
}
__device__ __forceinline__ void ldsm_x4t(uint32_t& r0, uint32_t& r1, uint32_t& r2,
                                         uint32_t& r3, uint32_t addr) {
    asm volatile("ldmatrix.sync.aligned.m8n8.x4.trans.shared.b16 {%0,%1,%2,%3}, [%4];"
                 : "=r"(r0), "=r"(r1), "=r"(r2), "=r"(r3) : "r"(addr));
}
__device__ __forceinline__ void mma_bf16(float* c, const uint32_t* a, const uint32_t* b) {
    asm volatile(
        "mma.sync.aligned.m16n8k16.row.col.f32.bf16.bf16.f32 "
        "{%0,%1,%2,%3}, {%4,%5,%6,%7}, {%8,%9}, {%0,%1,%2,%3};"
        : "+f"(c[0]), "+f"(c[1]), "+f"(c[2]), "+f"(c[3])
        : "r"(a[0]), "r"(a[1]), "r"(a[2]), "r"(a[3]), "r"(b[0]), "r"(b[1]));
}
// pack two floats -> bf16x2 (lo half = first arg)
__device__ __forceinline__ uint32_t packbf(float lo, float hi) {
    uint32_t d;
    asm("cvt.rn.bf16x2.f32 %0, %1, %2;" : "=r"(d) : "f"(hi), "f"(lo));
    return d;
}
__device__ __forceinline__ float bfr(float x) {
    return __bfloat162float(__float2bfloat16(x));
}

// ---------------- fp32 -> (bf16 hi, lo) pack kernels ----------------
__global__ __launch_bounds__(256) void pack_a(const float* __restrict__ x,
                                              __nv_bfloat16* __restrict__ y) {
    int idx = blockIdx.x * 256 + threadIdx.x;
    int m = idx >> 9;
    int j = (idx & 511) * 2;
    float2 v = *reinterpret_cast<const float2*>(x + (size_t)m * DIMX + j);
    __nv_bfloat16 h0 = __float2bfloat16(v.x), h1 = __float2bfloat16(v.y);
    __nv_bfloat16 l0 = __float2bfloat16(v.x - __bfloat162float(h0));
    __nv_bfloat16 l1 = __float2bfloat16(v.y - __bfloat162float(h1));
    __nv_bfloat162 h; h.x = h0; h.y = h1;
    __nv_bfloat162 l; l.x = l0; l.y = l1;
    size_t base = (size_t)m * KP;
    *reinterpret_cast<__nv_bfloat162*>(y + base + j) = h;
    *reinterpret_cast<__nv_bfloat162*>(y + base + DIMX + j) = h;
    *reinterpret_cast<__nv_bfloat162*>(y + base + 2 * DIMX + j) = l;
}
__global__ __launch_bounds__(256) void pack_b(const float* __restrict__ x,
                                              __nv_bfloat16* __restrict__ y) {
    int idx = blockIdx.x * 256 + threadIdx.x;
    int m = idx >> 9;
    int j = (idx & 511) * 2;
    float2 v = *reinterpret_cast<const float2*>(x + (size_t)m * DIMX + j);
    __nv_bfloat16 h0 = __float2bfloat16(v.x), h1 = __float2bfloat16(v.y);
    __nv_bfloat16 l0 = __float2bfloat16(v.x - __bfloat162float(h0));
    __nv_bfloat16 l1 = __float2bfloat16(v.y - __bfloat162float(h1));
    __nv_bfloat162 h; h.x = h0; h.y = h1;
    __nv_bfloat162 l; l.x = l0; l.y = l1;
    size_t base = (size_t)m * KP;
    *reinterpret_cast<__nv_bfloat162*>(y + base + j) = h;
    *reinterpret_cast<__nv_bfloat162*>(y + base + DIMX + j) = l;
    *reinterpret_cast<__nv_bfloat162*>(y + base + 2 * DIMX + j) = h;
}

// ---------------- warp-MMA GEMM (4-stage cp.async pipeline) ------------------
// C = (A2 @ B2^T + bias) * scale; output fp32 (Cf) or split-bf16 (Ph/Pl planes).
__global__ __launch_bounds__(256) void gemm_mma(const __nv_bfloat16* __restrict__ A,
                                                const __nv_bfloat16* __restrict__ B,
                                                const float* __restrict__ bias,
                                                float* __restrict__ Cf,
                                                __nv_bfloat16* __restrict__ Ph,
                                                __nv_bfloat16* __restrict__ Pl,
                                                float scale) {
    extern __shared__ __align__(16) char smem_g[];
    const uint32_t sbase = smem_u32(smem_g);
    const int tid = threadIdx.x;
    const int lane = tid & 31;
    const int wid = tid >> 5;
    const int wm = (wid & 3) * 32;
    const int wn = (wid >> 2) * 64;
    const int n0 = blockIdx.x * BN, m0 = blockIdx.y * BM;

    const __nv_bfloat16* Abase = A + (size_t)m0 * KP;
    const __nv_bfloat16* Bbase = B + (size_t)n0 * KP;

    const int r0_ = tid >> 2, r1_ = (tid + 256) >> 2;
    const int s0_ = (tid & 3) * 8;
    const uint32_t soffA0 = (uint32_t)(r0_ * 80 + (tid & 3) * 16);
    const uint32_t soffA1 = (uint32_t)(r1_ * 80 + (tid & 3) * 16);

    float acc[2][8][4] = {};

    auto load_stage = [&](int kt, int s) {
        uint32_t sa = sbase + (uint32_t)s * 20480u;
        uint32_t sb = sa + 10240u;
        const __nv_bfloat16* Ak = Abase + kt * BK;
        const __nv_bfloat16* Bk = Bbase + kt * BK;
        CP_ASYNC16(sa + soffA0, Ak + (size_t)r0_ * KP + s0_);
        CP_ASYNC16(sa + soffA1, Ak + (size_t)r1_ * KP + s0_);
        CP_ASYNC16(sb + soffA0, Bk + (size_t)r0_ * KP + s0_);
        CP_ASYNC16(sb + soffA1, Bk + (size_t)r1_ * KP + s0_);
        CP_COMMIT();
    };

    load_stage(0, 0);
    load_stage(1, 1);
    load_stage(2, 2);

    for (int kt = 0; kt < NKT; kt++) {
        if (kt < NKT - 2) { CP_WAIT(2); }
        else if (kt == NKT - 2) { CP_WAIT(1); }
        else { CP_WAIT(0); }
        __syncthreads();
        if (kt + 3 < NKT) load_stage(kt + 3, (kt + 3) & 3);

        uint32_t sa = sbase + (uint32_t)(kt & 3) * 20480u;
        uint32_t sb = sa + 10240u;
#pragma unroll
        for (int s = 0; s < 2; s++) {
            uint32_t aF[2][4], bF[8][2];
#pragma unroll
            for (int mf = 0; mf < 2; mf++) {
                uint32_t addr = sa + (uint32_t)((wm + mf * 16 + (lane & 15)) * 80 +
                                                s * 32 + (lane >> 4) * 16);
                ldsm_x4(aF[mf][0], aF[mf][1], aF[mf][2], aF[mf][3], addr);
            }
#pragma unroll
            for (int nf4 = 0; nf4 < 4; nf4++) {
                int nrow = wn + nf4 * 16 + ((lane >> 4) * 8) + (lane & 7);
                uint32_t addr = sb + (uint32_t)(nrow * 80 + s * 32 +
                                                (((lane >> 3) & 1) * 16));
                uint32_t q0, q1, q2, q3;
                ldsm_x4(q0, q1, q2, q3, addr);
                bF[nf4 * 2 + 0][0] = q0; bF[nf4 * 2 + 0][1] = q1;
                bF[nf4 * 2 + 1][0] = q2; bF[nf4 * 2 + 1][1] = q3;
            }
#pragma unroll
            for (int mf = 0; mf < 2; mf++)
#pragma unroll
                for (int nf = 0; nf < 8; nf++)
                    mma_bf16(acc[mf][nf], aF[mf], bF[nf]);
        }
    }

#pragma unroll
    for (int mf = 0; mf < 2; mf++) {
        int rbase = m0 + wm + mf * 16 + (lane >> 2);
#pragma unroll
        for (int nf = 0; nf < 8; nf++) {
            int col = n0 + wn + nf * 8 + (lane & 3) * 2;
            float2 bv = *reinterpret_cast<const float2*>(bias + col);
            float v00 = (acc[mf][nf][0] + bv.x) * scale;
            float v01 = (acc[mf][nf][1] + bv.y) * scale;
            float v10 = (acc[mf][nf][2] + bv.x) * scale;
            float v11 = (acc[mf][nf][3] + bv.y) * scale;
            if (Ph) {
                float h00 = bfr(v00), h01 = bfr(v01), h10 = bfr(v10), h11 = bfr(v11);
                size_t o0 = (size_t)rbase * DIMX + col;
                size_t o1 = (size_t)(rbase + 8) * DIMX + col;
                *reinterpret_cast<uint32_t*>(Ph + o0) = packbf(h00, h01);
                *reinterpret_cast<uint32_t*>(Pl + o0) = packbf(v00 - h00, v01 - h01);
                *reinterpret_cast<uint32_t*>(Ph + o1) = packbf(h10, h11);
                *reinterpret_cast<uint32_t*>(Pl + o1) = packbf(v10 - h10, v11 - h11);
            } else {
                float2 o0 = {v00, v01}, o1 = {v10, v11};
                *reinterpret_cast<float2*>(Cf + (size_t)rbase * DIMX + col) = o0;
                *reinterpret_cast<float2*>(Cf + (size_t)(rbase + 8) * DIMX + col) = o1;
            }
        }
    }
}

// ---------------- tensor-core flash attention --------------------------------
// smem byte offsets
#define AQH 0
#define AQL 18432
#define ASTG0 36864
#define STGB 73728
#define APL_KH 0
#define APL_KL 18432
#define APL_VH 36864
#define APL_VL 55296
#define AMX  184320
#define AKM0 185344
#define ATT_SMEM (185344 + 1024)

__global__ __launch_bounds__(256, 1) void attn_tc(const int* __restrict__ qm_g,
                                                  const int* __restrict__ km_g) {
    extern __shared__ __align__(16) char smem[];
    const uint32_t sb = smem_u32(smem);
    const int tid = threadIdx.x;
    const int lane = tid & 31;
    const int wid = tid >> 5;
    const int wm = (wid & 3) * 32;
    const int widn = wid >> 2;
    const int wnk = widn * 64;
    const int q0 = blockIdx.x * BQ;
    const int h = blockIdx.y;
    const int b = blockIdx.z;

    // ---- async loaders ----
    auto load_kv = [&](int kt2) {
        int s = kt2 & 1;
        int k0 = kt2 * BKT;
        uint32_t dstb = sb + ASTG0 + (uint32_t)s * STGB;
        size_t rowbase = (size_t)(b * KL + k0);
#pragma unroll
        for (int p = 0; p < 4; p++) {
            const __nv_bfloat16* sp = (p == 0) ? g_Kh : (p == 1) ? g_Kl
                                     : (p == 2) ? g_Vh : g_Vl;
            uint32_t dp = dstb + (uint32_t)p * 18432u;
#pragma unroll
            for (int i = 0; i < 4; i++) {
                int c = tid + i * 256;
                int row = c >> 3, ch = c & 7;
                CP_ASYNC16(dp + (uint32_t)(row * 144 + ch * 16),
                           sp + (((rowbase + row) << 10) + h * HD + ch * 8));
            }
        }
        if (tid < 32)
            CP_ASYNC16(sb + AKM0 + (uint32_t)(s * 512 + tid * 16),
                       km_g + b * KL + k0 + tid * 4);
    };

    // group0: Q planes + stage0 + km0
    {
        size_t rowbase = (size_t)(b * QL + q0);
#pragma unroll
        for (int p = 0; p < 2; p++) {
            const __nv_bfloat16* sp = p == 0 ? g_Qh : g_Ql;
            uint32_t dp = sb + (uint32_t)(p * 18432);
#pragma unroll
            for (int i = 0; i < 4; i++) {
                int c = tid + i * 256;
                int row = c >> 3, ch = c & 7;
                CP_ASYNC16(dp + (uint32_t)(row * 144 + ch * 16),
                           sp + (((rowbase + row) << 10) + h * HD + ch * 8));
            }
        }
        load_kv(0);
        CP_COMMIT();
        load_kv(1);
        CP_COMMIT();
    }

    // per-thread row masks / stats: rows (mf, half) = wm + mf*16 + (lane>>2) + half*8
    int qmr[2][2];
#pragma unroll
    for (int mf = 0; mf < 2; mf++)
#pragma unroll
        for (int hf = 0; hf < 2; hf++)
            qmr[mf][hf] = qm_g[b * QL + q0 + wm + mf * 16 + (lane >> 2) + hf * 8];

    float mrow[2][2], lrow[2][2], Oacc[2][8][4] = {};
#pragma unroll
    for (int mf = 0; mf < 2; mf++)
#pragma unroll
        for (int hf = 0; hf < 2; hf++) { mrow[mf][hf] = -FLT_MAX; lrow[mf][hf] = 0.0f; }

    float* mx = (float*)(smem + AMX);

    for (int kt = 0; kt < NT; kt++) {
        if (kt < NT - 1) { CP_WAIT(1); } else { CP_WAIT(0); }
        __syncthreads();
        const uint32_t kst = sb + ASTG0 + (uint32_t)(kt & 1) * STGB;
        const int* kms = (const int*)(smem + AKM0 + (kt & 1) * 512);

        int2 kmv[8];
#pragma unroll
        for (int nf = 0; nf < 8; nf++)
            kmv[nf] = *(const int2*)&kms[wnk + nf * 8 + (lane & 3) * 2];

        // ---- S = Q K^T (split: hh + hl + lh) ----
        float S[2][8][4] = {};
#pragma unroll
        for (int s16 = 0; s16 < 4; s16++) {
            uint32_t aH[2][4], aL[2][4];
#pragma unroll
            for (int mf = 0; mf < 2; mf++) {
                uint32_t ad = sb + (uint32_t)((wm + mf * 16 + (lane & 15)) * 144 +
                                              s16 * 32 + (lane >> 4) * 16);
                ldsm_x4(aH[mf][0], aH[mf][1], aH[mf][2], aH[mf][3], ad);
                ldsm_x4(aL[mf][0], aL[mf][1], aL[mf][2], aL[mf][3], ad + 18432u);
            }
            uint32_t bH[8][2], bL[8][2];
#pragma unroll
            for (int nf4 = 0; nf4 < 4; nf4++) {
                int nrow = wnk + nf4 * 16 + ((lane >> 4) * 8) + (lane & 7);
                uint32_t ad = kst + (uint32_t)(nrow * 144 + s16 * 32 +
                                               (((lane >> 3) & 1) * 16));
                uint32_t r0, r1, r2, r3;
                ldsm_x4(r0, r1, r2, r3, ad + APL_KH);
                bH[nf4 * 2 + 0][0] = r0; bH[nf4 * 2 + 0][1] = r1;
                bH[nf4 * 2 + 1][0] = r2; bH[nf4 * 2 + 1][1] = r3;
                ldsm_x4(r0, r1, r2, r3, ad + APL_KL);
                bL[nf4 * 2 + 0][0] = r0; bL[nf4 * 2 + 0][1] = r1;
                bL[nf4 * 2 + 1][0] = r2; bL[nf4 * 2 + 1][1] = r3;
            }
#pragma unroll
            for (int mf = 0; mf < 2; mf++)
#pragma unroll
                for (int nf = 0; nf < 8; nf++) {
                    mma_bf16(S[mf][nf], aH[mf], bH[nf]);
                    mma_bf16(S[mf][nf], aH[mf], bL[nf]);
                    mma_bf16(S[mf][nf], aL[mf], bH[nf]);
                }
        }

        // ---- mask + partial row max ----
        float tmax[2][2] = {{-FLT_MAX, -FLT_MAX}, {-FLT_MAX, -FLT_MAX}};
#pragma unroll
        for (int mf = 0; mf < 2; mf++)
#pragma unroll
            for (int nf = 0; nf < 8; nf++) {
                bool k0ok = kmv[nf].x != 0, k1ok = kmv[nf].y != 0;
                float s0 = (qmr[mf][0] && k0ok) ? S[mf][nf][0] : -FLT_MAX;
                float s1 = (qmr[mf][0] && k1ok) ? S[mf][nf][1] : -FLT_MAX;
                float s2 = (qmr[mf][1] && k0ok) ? S[mf][nf][2] : -FLT_MAX;
                float s3 = (qmr[mf][1] && k1ok) ? S[mf][nf][3] : -FLT_MAX;
                S[mf][nf][0] = s0; S[mf][nf][1] = s1;
                S[mf][nf][2] = s2; S[mf][nf][3] = s3;
                tmax[mf][0] = fmaxf(tmax[mf][0], fmaxf(s0, s1));
                tmax[mf][1] = fmaxf(tmax[mf][1], fmaxf(s2, s3));
            }
#pragma unroll
        for (int mf = 0; mf < 2; mf++)
#pragma unroll
            for (int hf = 0; hf < 2; hf++) {
                tmax[mf][hf] = fmaxf(tmax[mf][hf], __shfl_xor_sync(~0u, tmax[mf][hf], 1));
                tmax[mf][hf] = fmaxf(tmax[mf][hf], __shfl_xor_sync(~0u, tmax[mf][hf], 2));
            }
        if ((lane & 3) == 0) {
#pragma unroll
            for (int mf = 0; mf < 2; mf++)
#pragma unroll
                for (int hf = 0; hf < 2; hf++)
                    mx[widn * 128 + wm + mf * 16 + (lane >> 2) + hf * 8] = tmax[mf][hf];
        }
        __syncthreads();

        float alpha[2][2];
#pragma unroll
        for (int mf = 0; mf < 2; mf++)
#pragma unroll
            for (int hf = 0; hf < 2; hf++) {
                float other = mx[(1 - widn) * 128 + wm + mf * 16 + (lane >> 2) + hf * 8];
                float mnew = fmaxf(mrow[mf][hf], fmaxf(tmax[mf][hf], other));
                alpha[mf][hf] = __expf(mrow[mf][hf] - mnew);
                mrow[mf][hf] = mnew;
            }

        // ---- P = exp(S - m), partial row sums, rescale O ----
        float rs[2][2] = {};
#pragma unroll
        for (int mf = 0; mf < 2; mf++)
#pragma unroll
            for (int nf = 0; nf < 8; nf++) {
                float p0 = __expf(S[mf][nf][0] - mrow[mf][0]);
                float p1 = __expf(S[mf][nf][1] - mrow[mf][0]);
                float p2 = __expf(S[mf][nf][2] - mrow[mf][1]);
                float p3 = __expf(S[mf][nf][3] - mrow[mf][1]);
                S[mf][nf][0] = p0; S[mf][nf][1] = p1;
                S[mf][nf][2] = p2; S[mf][nf][3] = p3;
                rs[mf][0] += p0 + p1;
                rs[mf][1] += p2 + p3;
            }
#pragma unroll
        for (int mf = 0; mf < 2; mf++)
#pragma unroll
            for (int hf = 0; hf < 2; hf++) {
                rs[mf][hf] += __shfl_xor_sync(~0u, rs[mf][hf], 1);
                rs[mf][hf] += __shfl_xor_sync(~0u, rs[mf][hf], 2);
                lrow[mf][hf] = lrow[mf][hf] * alpha[mf][hf] + rs[mf][hf];
            }
#pragma unroll
        for (int mf = 0; mf < 2; mf++)
#pragma unroll
            for (int nf = 0; nf < 8; nf++) {
                Oacc[mf][nf][0] *= alpha[mf][0];
                Oacc[mf][nf][1] *= alpha[mf][0];
                Oacc[mf][nf][2] *= alpha[mf][1];
                Oacc[mf][nf][3] *= alpha[mf][1];
            }

        // ---- convert P to bf16 hi/lo A-fragments ----
        uint32_t PaH[2][4][4], PaL[2][4][4];
#pragma unroll
        for (int mf = 0; mf < 2; mf++)
#pragma unroll
            for (int j = 0; j < 4; j++) {
#pragma unroll
                for (int half = 0; half < 2; half++) {  // half: nf block 2j / 2j+1
                    const float* sv = S[mf][2 * j + half];
                    float h0 = bfr(sv[0]), h1 = bfr(sv[1]);
                    float h2 = bfr(sv[2]), h3 = bfr(sv[3]);
                    PaH[mf][j][half * 2 + 0] = packbf(h0, h1);
                    PaH[mf][j][half * 2 + 1] = packbf(h2, h3);
                    PaL[mf][j][half * 2 + 0] = packbf(sv[0] - h0, sv[1] - h1);
                    PaL[mf][j][half * 2 + 1] = packbf(sv[2] - h2, sv[3] - h3);
                }
            }

        // ---- O += P V (split) ----
#pragma unroll
        for (int j = 0; j < 4; j++) {
            uint32_t vH[8][2], vL[8][2];
#pragma unroll
            for (int g = 0; g < 4; g++) {
                int vrow = wnk + j * 16 + ((lane >> 3) & 1) * 8 + (lane & 7);
                uint32_t ad = kst + (uint32_t)(vrow * 144 + g * 32 + (lane >> 4) * 16);
                uint32_t r0, r1, r2, r3;
                ldsm_x4t(r0, r1, r2, r3, ad + APL_VH);
                vH[g * 2 + 0][0] = r0; vH[g * 2 + 0][1] = r1;
                vH[g * 2 + 1][0] = r2; vH[g * 2 + 1][1] = r3;
                ldsm_x4t(r0, r1, r2, r3, ad + APL_VL);
                vL[g * 2 + 0][0] = r0; vL[g * 2 + 0][1] = r1;
                vL[g * 2 + 1][0] = r2; vL[g * 2 + 1][1] = r3;
            }
#pragma unroll
            for (int mf = 0; mf < 2; mf++)
#pragma unroll
                for (int nf = 0; nf < 8; nf++) {
                    mma_bf16(Oacc[mf][nf], PaH[mf][j], vH[nf]);
                    mma_bf16(Oacc[mf][nf], PaH[mf][j], vL[nf]);
                    mma_bf16(Oacc[mf][nf], PaL[mf][j], vH[nf]);
                }
        }
        __syncthreads();
        if (kt + 2 < NT) { load_kv(kt + 2); CP_COMMIT(); }
    }

    // ---- combine warp pairs, normalize, write split-bf16 to g_o2 ----
    float* Op = (float*)(smem + ASTG0 + (wid & 3) * 8192);
    float* lp = (float*)(smem + AMX);
    if (widn == 0) {
        if ((lane & 3) == 0) {
#pragma unroll
            for (int mf = 0; mf < 2; mf++)
#pragma unroll
                for (int hf = 0; hf < 2; hf++)
                    lp[wm + mf * 16 + (lane >> 2) + hf * 8] = lrow[mf][hf];
        }
#pragma unroll
        for (int mf = 0; mf < 2; mf++) {
            int r0 = mf * 16 + (lane >> 2);
#pragma unroll
            for (int nf = 0; nf < 8; nf++) {
                int col = nf * 8 + (lane & 3) * 2;
                *(float2*)&Op[r0 * 64 + col] =
                    make_float2(Oacc[mf][nf][0], Oacc[mf][nf][1]);
                *(float2*)&Op[(r0 + 8) * 64 + col] =
                    make_float2(Oacc[mf][nf][2], Oacc[mf][nf][3]);
            }
        }
    }
    __syncthreads();
    if (widn == 1) {
#pragma unroll
        for (int mf = 0; mf < 2; mf++) {
            int r0 = mf * 16 + (lane >> 2);
            float inv0 = 1.0f / (lrow[mf][0] + lp[wm + r0]);
            float inv1 = 1.0f / (lrow[mf][1] + lp[wm + r0 + 8]);
            size_t gr0 = (size_t)(b * QL + q0 + wm + r0) * KP;
            size_t gr1 = gr0 + (size_t)8 * KP;
#pragma unroll
            for (int nf = 0; nf < 8; nf++) {
                int col = nf * 8 + (lane & 3) * 2;
                float2 p0 = *(float2*)&Op[r0 * 64 + col];
                float2 p1 = *(float2*)&Op[(r0 + 8) * 64 + col];
                float o00 = (Oacc[mf][nf][0] + p0.x) * inv0;
                float o01 = (Oacc[mf][nf][1] + p0.y) * inv0;
                float o10 = (Oacc[mf][nf][2] + p1.x) * inv1;
                float o11 = (Oacc[mf][nf][3] + p1.y) * inv1;
                float h00 = bfr(o00), h01 = bfr(o01), h10 = bfr(o10), h11 = bfr(o11);
                uint32_t HI0 = packbf(h00, h01), LO0 = packbf(o00 - h00, o01 - h01);
                uint32_t HI1 = packbf(h10, h11), LO1 = packbf(o10 - h10, o11 - h11);
                __nv_bfloat16* pr0 = g_o2 + gr0 + h * HD + col;
                __nv_bfloat16* pr1 = g_o2 + gr1 + h * HD + col;
                *(uint32_t*)(pr0) = HI0;
                *(uint32_t*)(pr0 + DIMX) = HI0;
                *(uint32_t*)(pr0 + 2 * DIMX) = LO0;
                *(uint32_t*)(pr1) = HI1;
                *(uint32_t*)(pr1 + DIMX) = HI1;
                *(uint32_t*)(pr1 + 2 * DIMX) = LO1;
            }
        }
    }
}

// ---------------- host side ----------------
extern "C" void kernel_launch(void* const* d_in, const int* in_sizes, int n_in,
                              void* d_out, int out_size) {
    const float* q = nullptr;
    const float* k = nullptr;
    const int* qm = nullptr;
    const int* km = nullptr;
    for (int i = 0; i < 4; i++) {
        int s = in_sizes[i];
        if (s == BS * QL * DIMX)      q  = (const float*)d_in[i];
        else if (s == BS * KL * DIMX) k  = (const float*)d_in[i];
        else if (s == BS * QL)        qm = (const int*)d_in[i];
        else if (s == BS * KL)        km = (const int*)d_in[i];
    }
    const float* Wq = (const float*)d_in[4];
    const float* bq = (const float*)d_in[5];
    const float* Wk = (const float*)d_in[6];
    const float* bk = (const float*)d_in[7];
    const float* Wv = (const float*)d_in[8];
    const float* bv = (const float*)d_in[9];
    const float* Wo = (const float*)d_in[10];
    const float* bo = (const float*)d_in[11];
    float* out = (float*)d_out;

    __nv_bfloat16 *q2, *k2, *o2, *wq2, *wk2, *wv2, *wo2;
    __nv_bfloat16 *Qh, *Ql, *Kh, *Kl, *Vh, *Vl;
    cudaGetSymbolAddress((void**)&q2, g_q2);
    cudaGetSymbolAddress((void**)&k2, g_k2);
    cudaGetSymbolAddress((void**)&o2, g_o2);
    cudaGetSymbolAddress((void**)&wq2, g_Wq2);
    cudaGetSymbolAddress((void**)&wk2, g_Wk2);
    cudaGetSymbolAddress((void**)&wv2, g_Wv2);
    cudaGetSymbolAddress((void**)&wo2, g_Wo2);
    cudaGetSymbolAddress((void**)&Qh, g_Qh);
    cudaGetSymbolAddress((void**)&Ql, g_Ql);
    cudaGetSymbolAddress((void**)&Kh, g_Kh);
    cudaGetSymbolAddress((void**)&Kl, g_Kl);
    cudaGetSymbolAddress((void**)&Vh, g_Vh);
    cudaGetSymbolAddress((void**)&Vl, g_Vl);

    static int configured = 0;
    cudaFuncSetAttribute(gemm_mma, cudaFuncAttributeMaxDynamicSharedMemorySize,
                         GSTG * 20480);
    cudaFuncSetAttribute(attn_tc, cudaFuncAttributeMaxDynamicSharedMemorySize,
                         ATT_SMEM);
    (void)configured;

    // ---- pack weights + activations ----
    pack_b<<<DIMX * DIMX / 512, 256>>>(Wq, wq2);
    pack_b<<<DIMX * DIMX / 512, 256>>>(Wk, wk2);
    pack_b<<<DIMX * DIMX / 512, 256>>>(Wv, wv2);
    pack_b<<<DIMX * DIMX / 512, 256>>>(Wo, wo2);
    pack_a<<<BS * QL * DIMX / 512, 256>>>(q, q2);
    pack_a<<<BS * KL * DIMX / 512, 256>>>(k, k2);

    // ---- projections -> split-bf16 planes ----
    gemm_mma<<<dim3(DIMX / BN, BS * QL / BM), 256, GSTG * 20480>>>(
        q2, wq2, bq, nullptr, Qh, Ql, 0.125f);
    gemm_mma<<<dim3(DIMX / BN, BS * KL / BM), 256, GSTG * 20480>>>(
        k2, wk2, bk, nullptr, Kh, Kl, 1.0f);
    gemm_mma<<<dim3(DIMX / BN, BS * KL / BM), 256, GSTG * 20480>>>(
        k2, wv2, bv, nullptr, Vh, Vl, 1.0f);

    // ---- flash attention (tensor cores) -> g_o2 (split layout) ----
    attn_tc<<<dim3(QL / BQ, NH, BS), 256, ATT_SMEM>>>(qm, km);

    // ---- output projection -> fp32 out ----
    gemm_mma<<<dim3(DIMX / BN, BS * QL / BM), 256, GSTG * 20480>>>(
        o2, wo2, bo, out, nullptr, nullptr, 1.0f);
}

// round 5
// speedup vs baseline: 3.4988x; 1.2781x over previous
#include <cuda_runtime.h>
#include <cuda_bf16.h>
#include <float.h>
#include <stdint.h>

#define DIMX 1024
#define NH 16
#define HD 64
#define QL 1024
#define KL 4096
#define BS 2

#define KP 3072            // packed K' = 3 * 1024 (bf16 split: hh + hl + lh)
#define BM 128
#define BN 128
#define BK 32
#define NKT (KP / BK)      // 96 k-tiles
#define GSTG 4             // gemm pipeline stages

// attention tiling
#define BQ 128
#define BKT 128

// ---------------- scratch (__device__ globals; no allocation) ----------------
__device__ __nv_bfloat16 g_q2[BS * QL * KP];
__device__ __nv_bfloat16 g_k2[BS * KL * KP];      // COMPACTED rows
__device__ __nv_bfloat16 g_o2[BS * QL * KP];
__device__ __nv_bfloat16 g_Wq2[DIMX * KP];
__device__ __nv_bfloat16 g_Wk2[DIMX * KP];
__device__ __nv_bfloat16 g_Wv2[DIMX * KP];
__device__ __nv_bfloat16 g_Wo2[DIMX * KP];

// projection outputs as split-bf16 planes (K/V in compacted row space)
__device__ __nv_bfloat16 g_Qh[BS * QL * DIMX];
__device__ __nv_bfloat16 g_Ql[BS * QL * DIMX];
__device__ __nv_bfloat16 g_Kh[BS * KL * DIMX];
__device__ __nv_bfloat16 g_Kl[BS * KL * DIMX];
__device__ __nv_bfloat16 g_Vh[BS * KL * DIMX];
__device__ __nv_bfloat16 g_Vl[BS * KL * DIMX];

// compaction metadata
__device__ int g_cnt[BS];
__device__ int g_cidx[BS * KL];
__device__ int g_cmask[BS * KL];
__device__ float g_kmean[BS * DIMX];
__device__ float g_meanv[BS * DIMX];

// ---------------- low-level helpers (baseline sm_80-era PTX only) ------------
__device__ __forceinline__ uint32_t smem_u32(const void* p) {
    uint32_t a;
    asm("{ .reg .u64 t; cvta.to.shared.u64 t, %1; cvt.u32.u64 %0, t; }" : "=r"(a) : "l"(p));
    return a;
}
#define CP_ASYNC16(dst, src) \
    asm volatile("cp.async.cg.shared.global [%0], [%1], 16;" :: "r"(dst), "l"(src))
#define CP_COMMIT() asm volatile("cp.async.commit_group;" ::: "memory")
#define CP_WAIT(n)  asm volatile("cp.async.wait_group %0;" :: "n"(n) : "memory")

__device__ __forceinline__ void ldsm_x4(uint32_t& r0, uint32_t& r1, uint32_t& r2,
                                        uint32_t& r3, uint32_t addr) {
    asm volatile("ldmatrix.sync.aligned.m8n8.x4.shared.b16 {%0,%1,%2,%3}, [%4];"
                 : "=r"(r0), "=r"(r1), "=r"(r2), "=r"(r3) : "r"(addr));
}
__device__ __forceinline__ void ldsm_x4t(uint32_t& r0, uint32_t& r1, uint32_t& r2,
                                         uint32_t& r3, uint32_t addr) {
    asm volatile("ldmatrix.sync.aligned.m8n8.x4.trans.shared.b16 {%0,%1,%2,%3}, [%4];"
                 : "=r"(r0), "=r"(r1), "=r"(r2), "=r"(r3) : "r"(addr));
}
__device__ __forceinline__ void mma_bf16(float* c, const uint32_t* a, const uint32_t* b) {
    asm volatile(
        "mma.sync.aligned.m16n8k16.row.col.f32.bf16.bf16.f32 "
        "{%0,%1,%2,%3}, {%4,%5,%6,%7}, {%8,%9}, {%0,%1,%2,%3};"
        : "+f"(c[0]), "+f"(c[1]), "+f"(c[2]), "+f"(c[3])
        : "r"(a[0]), "r"(a[1]), "r"(a[2]), "r"(a[3]), "r"(b[0]), "r"(b[1]));
}
__device__ __forceinline__ uint32_t packbf(float lo, float hi) {
    uint32_t d;
    asm("cvt.rn.bf16x2.f32 %0, %1, %2;" : "=r"(d) : "f"(hi), "f"(lo));
    return d;
}
__device__ __forceinline__ float bfr(float x) {
    return __bfloat162float(__float2bfloat16(x));
}

// ---------------- compaction: deterministic prefix scan of k_m ---------------
__global__ __launch_bounds__(1024) void compact_scan(const int* __restrict__ km) {
    __shared__ int ssum[1024];
    const int b = blockIdx.x;
    const int t = threadIdx.x;
    int v[4], s = 0;
#pragma unroll
    for (int i = 0; i < 4; i++) {
        v[i] = km[b * KL + t * 4 + i] != 0 ? 1 : 0;
        s += v[i];
    }
    ssum[t] = s;
    __syncthreads();
    for (int off = 1; off < 1024; off <<= 1) {
        int x = (t >= off) ? ssum[t - off] : 0;
        __syncthreads();
        ssum[t] += x;
        __syncthreads();
    }
    int pos = ssum[t] - s;  // exclusive prefix
#pragma unroll
    for (int i = 0; i < 4; i++) {
        if (v[i]) { g_cidx[b * KL + pos] = t * 4 + i; pos++; }
    }
    int total = ssum[1023];
    if (t == 0) g_cnt[b] = total;
#pragma unroll
    for (int i = 0; i < 4; i++) {
        int idx = t * 4 + i;
        g_cmask[b * KL + idx] = (idx < total) ? 1 : 0;
    }
}

// column mean of raw k over all KL rows
__global__ __launch_bounds__(256) void colmean(const float* __restrict__ k) {
    const int j = blockIdx.x * 256 + threadIdx.x;
    const int b = blockIdx.y;
    const float* p = k + (size_t)b * KL * DIMX + j;
    float s0 = 0, s1 = 0, s2 = 0, s3 = 0;
    for (int kk = 0; kk < KL; kk += 4) {
        s0 += p[(size_t)kk * DIMX];
        s1 += p[(size_t)(kk + 1) * DIMX];
        s2 += p[(size_t)(kk + 2) * DIMX];
        s3 += p[(size_t)(kk + 3) * DIMX];
    }
    g_kmean[b * DIMX + j] = (s0 + s1 + s2 + s3) * (1.0f / KL);
}

// meanv[b][d] = kmean[b] . Wv[d] + bv[d]   (warp per output row)
__global__ __launch_bounds__(256) void meanv_gemv(const float* __restrict__ Wv,
                                                  const float* __restrict__ bv) {
    const int b = blockIdx.y;
    const int lane = threadIdx.x & 31;
    const int d = blockIdx.x * 8 + (threadIdx.x >> 5);
    const float* w = Wv + (size_t)d * DIMX;
    const float* m = g_kmean + b * DIMX;
    float s = 0;
    for (int j = lane; j < DIMX; j += 32) s += m[j] * w[j];
#pragma unroll
    for (int off = 16; off > 0; off >>= 1) s += __shfl_xor_sync(~0u, s, off);
    if (lane == 0) g_meanv[b * DIMX + d] = s + bv[d];
}

// ---------------- fp32 -> packed split-bf16 kernels ----------------
__global__ __launch_bounds__(256) void pack_a(const float* __restrict__ x,
                                              __nv_bfloat16* __restrict__ y) {
    int idx = blockIdx.x * 256 + threadIdx.x;
    int m = idx >> 9;
    int j = (idx & 511) * 2;
    float2 v = *reinterpret_cast<const float2*>(x + (size_t)m * DIMX + j);
    __nv_bfloat16 h0 = __float2bfloat16(v.x), h1 = __float2bfloat16(v.y);
    __nv_bfloat16 l0 = __float2bfloat16(v.x - __bfloat162float(h0));
    __nv_bfloat16 l1 = __float2bfloat16(v.y - __bfloat162float(h1));
    __nv_bfloat162 h; h.x = h0; h.y = h1;
    __nv_bfloat162 l; l.x = l0; l.y = l1;
    size_t base = (size_t)m * KP;
    *reinterpret_cast<__nv_bfloat162*>(y + base + j) = h;
    *reinterpret_cast<__nv_bfloat162*>(y + base + DIMX + j) = h;
    *reinterpret_cast<__nv_bfloat162*>(y + base + 2 * DIMX + j) = l;
}
// gather active k rows (compacted) + zero pad, packed layout
__global__ __launch_bounds__(256) void gather_pack_k(const float* __restrict__ k) {
    int idx = blockIdx.x * 256 + threadIdx.x;
    int m = idx >> 9;              // compact row (global)
    int j = (idx & 511) * 2;
    int b = m >> 12;               // KL = 4096
    int i = m & (KL - 1);
    float2 v = {0.0f, 0.0f};
    if (i < g_cnt[b]) {
        int src = g_cidx[b * KL + i];
        v = *reinterpret_cast<const float2*>(k + ((size_t)(b * KL + src)) * DIMX + j);
    }
    __nv_bfloat16 h0 = __float2bfloat16(v.x), h1 = __float2bfloat16(v.y);
    __nv_bfloat16 l0 = __float2bfloat16(v.x - __bfloat162float(h0));
    __nv_bfloat16 l1 = __float2bfloat16(v.y - __bfloat162float(h1));
    __nv_bfloat162 h; h.x = h0; h.y = h1;
    __nv_bfloat162 l; l.x = l0; l.y = l1;
    size_t base = (size_t)m * KP;
    *reinterpret_cast<__nv_bfloat162*>(g_k2 + base + j) = h;
    *reinterpret_cast<__nv_bfloat162*>(g_k2 + base + DIMX + j) = h;
    *reinterpret_cast<__nv_bfloat162*>(g_k2 + base + 2 * DIMX + j) = l;
}
__global__ __launch_bounds__(256) void pack_b(const float* __restrict__ x,
                                              __nv_bfloat16* __restrict__ y) {
    int idx = blockIdx.x * 256 + threadIdx.x;
    int m = idx >> 9;
    int j = (idx & 511) * 2;
    float2 v = *reinterpret_cast<const float2*>(x + (size_t)m * DIMX + j);
    __nv_bfloat16 h0 = __float2bfloat16(v.x), h1 = __float2bfloat16(v.y);
    __nv_bfloat16 l0 = __float2bfloat16(v.x - __bfloat162float(h0));
    __nv_bfloat16 l1 = __float2bfloat16(v.y - __bfloat162float(h1));
    __nv_bfloat162 h; h.x = h0; h.y = h1;
    __nv_bfloat162 l; l.x = l0; l.y = l1;
    size_t base = (size_t)m * KP;
    *reinterpret_cast<__nv_bfloat162*>(y + base + j) = h;
    *reinterpret_cast<__nv_bfloat162*>(y + base + DIMX + j) = l;
    *reinterpret_cast<__nv_bfloat162*>(y + base + 2 * DIMX + j) = h;
}

// ---------------- warp-MMA GEMM (4-stage cp.async pipeline) ------------------
// cnt != nullptr => rows are per-batch compacted (4096 row space); skip CTAs
// entirely beyond the padded active count.
__global__ __launch_bounds__(256) void gemm_mma(const __nv_bfloat16* __restrict__ A,
                                                const __nv_bfloat16* __restrict__ B,
                                                const float* __restrict__ bias,
                                                float* __restrict__ Cf,
                                                __nv_bfloat16* __restrict__ Ph,
                                                __nv_bfloat16* __restrict__ Pl,
                                                float scale,
                                                const int* __restrict__ cnt) {
    extern __shared__ __align__(16) char smem_g[];
    const uint32_t sbase = smem_u32(smem_g);
    const int tid = threadIdx.x;
    const int lane = tid & 31;
    const int wid = tid >> 5;
    const int wm = (wid & 3) * 32;
    const int wn = (wid >> 2) * 64;
    const int n0 = blockIdx.x * BN, m0 = blockIdx.y * BM;

    if (cnt) {
        int b = m0 >> 12;              // 4096 rows per batch
        int local = m0 & (KL - 1);
        int padded = (cnt[b] + 127) & ~127;
        if (local >= padded) return;
    }

    const __nv_bfloat16* Abase = A + (size_t)m0 * KP;
    const __nv_bfloat16* Bbase = B + (size_t)n0 * KP;

    const int r0_ = tid >> 2, r1_ = (tid + 256) >> 2;
    const int s0_ = (tid & 3) * 8;
    const uint32_t soffA0 = (uint32_t)(r0_ * 80 + (tid & 3) * 16);
    const uint32_t soffA1 = (uint32_t)(r1_ * 80 + (tid & 3) * 16);

    float acc[2][8][4] = {};

    auto load_stage = [&](int kt, int s) {
        uint32_t sa = sbase + (uint32_t)s * 20480u;
        uint32_t sb = sa + 10240u;
        const __nv_bfloat16* Ak = Abase + kt * BK;
        const __nv_bfloat16* Bk = Bbase + kt * BK;
        CP_ASYNC16(sa + soffA0, Ak + (size_t)r0_ * KP + s0_);
        CP_ASYNC16(sa + soffA1, Ak + (size_t)r1_ * KP + s0_);
        CP_ASYNC16(sb + soffA0, Bk + (size_t)r0_ * KP + s0_);
        CP_ASYNC16(sb + soffA1, Bk + (size_t)r1_ * KP + s0_);
        CP_COMMIT();
    };

    load_stage(0, 0);
    load_stage(1, 1);
    load_stage(2, 2);

    for (int kt = 0; kt < NKT; kt++) {
        if (kt < NKT - 2) { CP_WAIT(2); }
        else if (kt == NKT - 2) { CP_WAIT(1); }
        else { CP_WAIT(0); }
        __syncthreads();
        if (kt + 3 < NKT) load_stage(kt + 3, (kt + 3) & 3);

        uint32_t sa = sbase + (uint32_t)(kt & 3) * 20480u;
        uint32_t sb = sa + 10240u;
#pragma unroll
        for (int s = 0; s < 2; s++) {
            uint32_t aF[2][4], bF[8][2];
#pragma unroll
            for (int mf = 0; mf < 2; mf++) {
                uint32_t addr = sa + (uint32_t)((wm + mf * 16 + (lane & 15)) * 80 +
                                                s * 32 + (lane >> 4) * 16);
                ldsm_x4(aF[mf][0], aF[mf][1], aF[mf][2], aF[mf][3], addr);
            }
#pragma unroll
            for (int nf4 = 0; nf4 < 4; nf4++) {
                int nrow = wn + nf4 * 16 + ((lane >> 4) * 8) + (lane & 7);
                uint32_t addr = sb + (uint32_t)(nrow * 80 + s * 32 +
                                                (((lane >> 3) & 1) * 16));
                uint32_t q0, q1, q2, q3;
                ldsm_x4(q0, q1, q2, q3, addr);
                bF[nf4 * 2 + 0][0] = q0; bF[nf4 * 2 + 0][1] = q1;
                bF[nf4 * 2 + 1][0] = q2; bF[nf4 * 2 + 1][1] = q3;
            }
#pragma unroll
            for (int mf = 0; mf < 2; mf++)
#pragma unroll
                for (int nf = 0; nf < 8; nf++)
                    mma_bf16(acc[mf][nf], aF[mf], bF[nf]);
        }
    }

#pragma unroll
    for (int mf = 0; mf < 2; mf++) {
        int rbase = m0 + wm + mf * 16 + (lane >> 2);
#pragma unroll
        for (int nf = 0; nf < 8; nf++) {
            int col = n0 + wn + nf * 8 + (lane & 3) * 2;
            float2 bv = *reinterpret_cast<const float2*>(bias + col);
            float v00 = (acc[mf][nf][0] + bv.x) * scale;
            float v01 = (acc[mf][nf][1] + bv.y) * scale;
            float v10 = (acc[mf][nf][2] + bv.x) * scale;
            float v11 = (acc[mf][nf][3] + bv.y) * scale;
            if (Ph) {
                float h00 = bfr(v00), h01 = bfr(v01), h10 = bfr(v10), h11 = bfr(v11);
                size_t o0 = (size_t)rbase * DIMX + col;
                size_t o1 = (size_t)(rbase + 8) * DIMX + col;
                *reinterpret_cast<uint32_t*>(Ph + o0) = packbf(h00, h01);
                *reinterpret_cast<uint32_t*>(Pl + o0) = packbf(v00 - h00, v01 - h01);
                *reinterpret_cast<uint32_t*>(Ph + o1) = packbf(h10, h11);
                *reinterpret_cast<uint32_t*>(Pl + o1) = packbf(v10 - h10, v11 - h11);
            } else {
                float2 o0 = {v00, v01}, o1 = {v10, v11};
                *reinterpret_cast<float2*>(Cf + (size_t)rbase * DIMX + col) = o0;
                *reinterpret_cast<float2*>(Cf + (size_t)(rbase + 8) * DIMX + col) = o1;
            }
        }
    }
}

// ---------------- tensor-core flash attention (compacted keys) ---------------
#define AQH 0
#define AQL 18432
#define ASTG0 36864
#define STGB 73728
#define APL_KH 0
#define APL_KL 18432
#define APL_VH 36864
#define APL_VL 55296
#define AMX  184320
#define AKM0 185344
#define ATT_SMEM (185344 + 1024)

__global__ __launch_bounds__(256, 1) void attn_tc(const int* __restrict__ qm_g,
                                                  const int* __restrict__ cnt,
                                                  const float* __restrict__ meanv) {
    extern __shared__ __align__(16) char smem[];
    const uint32_t sb = smem_u32(smem);
    const int tid = threadIdx.x;
    const int lane = tid & 31;
    const int wid = tid >> 5;
    const int wm = (wid & 3) * 32;
    const int widn = wid >> 2;
    const int wnk = widn * 64;
    const int q0 = blockIdx.x * BQ;
    const int h = blockIdx.y;
    const int b = blockIdx.z;

    const int NTa = (cnt[b] + BKT - 1) >> 7;   // active k-tiles

    auto load_kv = [&](int kt2) {
        int s = kt2 & 1;
        int k0 = kt2 * BKT;
        uint32_t dstb = sb + ASTG0 + (uint32_t)s * STGB;
        size_t rowbase = (size_t)(b * KL + k0);
#pragma unroll
        for (int p = 0; p < 4; p++) {
            const __nv_bfloat16* sp = (p == 0) ? g_Kh : (p == 1) ? g_Kl
                                     : (p == 2) ? g_Vh : g_Vl;
            uint32_t dp = dstb + (uint32_t)p * 18432u;
#pragma unroll
            for (int i = 0; i < 4; i++) {
                int c = tid + i * 256;
                int row = c >> 3, ch = c & 7;
                CP_ASYNC16(dp + (uint32_t)(row * 144 + ch * 16),
                           sp + (((rowbase + row) << 10) + h * HD + ch * 8));
            }
        }
        if (tid < 32)
            CP_ASYNC16(sb + AKM0 + (uint32_t)(s * 512 + tid * 16),
                       g_cmask + b * KL + k0 + tid * 4);
    };

    {
        size_t rowbase = (size_t)(b * QL + q0);
#pragma unroll
        for (int p = 0; p < 2; p++) {
            const __nv_bfloat16* sp = p == 0 ? g_Qh : g_Ql;
            uint32_t dp = sb + (uint32_t)(p * 18432);
#pragma unroll
            for (int i = 0; i < 4; i++) {
                int c = tid + i * 256;
                int row = c >> 3, ch = c & 7;
                CP_ASYNC16(dp + (uint32_t)(row * 144 + ch * 16),
                           sp + (((rowbase + row) << 10) + h * HD + ch * 8));
            }
        }
        load_kv(0);
        CP_COMMIT();
        load_kv(1 < NTa ? 1 : 0);
        CP_COMMIT();
    }

    int qmr[2][2];
#pragma unroll
    for (int mf = 0; mf < 2; mf++)
#pragma unroll
        for (int hf = 0; hf < 2; hf++)
            qmr[mf][hf] = qm_g[b * QL + q0 + wm + mf * 16 + (lane >> 2) + hf * 8];

    float mrow[2][2], lrow[2][2], Oacc[2][8][4] = {};
#pragma unroll
    for (int mf = 0; mf < 2; mf++)
#pragma unroll
        for (int hf = 0; hf < 2; hf++) { mrow[mf][hf] = -FLT_MAX; lrow[mf][hf] = 0.0f; }

    float* mx = (float*)(smem + AMX);

    for (int kt = 0; kt < NTa; kt++) {
        if (kt < NTa - 1) { CP_WAIT(1); } else { CP_WAIT(0); }
        __syncthreads();
        const uint32_t kst = sb + ASTG0 + (uint32_t)(kt & 1) * STGB;
        const int* kms = (const int*)(smem + AKM0 + (kt & 1) * 512);

        int2 kmv[8];
#pragma unroll
        for (int nf = 0; nf < 8; nf++)
            kmv[nf] = *(const int2*)&kms[wnk + nf * 8 + (lane & 3) * 2];

        float S[2][8][4] = {};
#pragma unroll
        for (int s16 = 0; s16 < 4; s16++) {
            uint32_t aH[2][4], aL[2][4];
#pragma unroll
            for (int mf = 0; mf < 2; mf++) {
                uint32_t ad = sb + (uint32_t)((wm + mf * 16 + (lane & 15)) * 144 +
                                              s16 * 32 + (lane >> 4) * 16);
                ldsm_x4(aH[mf][0], aH[mf][1], aH[mf][2], aH[mf][3], ad);
                ldsm_x4(aL[mf][0], aL[mf][1], aL[mf][2], aL[mf][3], ad + 18432u);
            }
            uint32_t bH[8][2], bL[8][2];
#pragma unroll
            for (int nf4 = 0; nf4 < 4; nf4++) {
                int nrow = wnk + nf4 * 16 + ((lane >> 4) * 8) + (lane & 7);
                uint32_t ad = kst + (uint32_t)(nrow * 144 + s16 * 32 +
                                               (((lane >> 3) & 1) * 16));
                uint32_t r0, r1, r2, r3;
                ldsm_x4(r0, r1, r2, r3, ad + APL_KH);
                bH[nf4 * 2 + 0][0] = r0; bH[nf4 * 2 + 0][1] = r1;
                bH[nf4 * 2 + 1][0] = r2; bH[nf4 * 2 + 1][1] = r3;
                ldsm_x4(r0, r1, r2, r3, ad + APL_KL);
                bL[nf4 * 2 + 0][0] = r0; bL[nf4 * 2 + 0][1] = r1;
                bL[nf4 * 2 + 1][0] = r2; bL[nf4 * 2 + 1][1] = r3;
            }
#pragma unroll
            for (int mf = 0; mf < 2; mf++)
#pragma unroll
                for (int nf = 0; nf < 8; nf++) {
                    mma_bf16(S[mf][nf], aH[mf], bH[nf]);
                    mma_bf16(S[mf][nf], aH[mf], bL[nf]);
                    mma_bf16(S[mf][nf], aL[mf], bH[nf]);
                }
        }

        float tmax[2][2] = {{-FLT_MAX, -FLT_MAX}, {-FLT_MAX, -FLT_MAX}};
#pragma unroll
        for (int mf = 0; mf < 2; mf++)
#pragma unroll
            for (int nf = 0; nf < 8; nf++) {
                bool k0ok = kmv[nf].x != 0, k1ok = kmv[nf].y != 0;
                float s0 = (qmr[mf][0] && k0ok) ? S[mf][nf][0] : -FLT_MAX;
                float s1 = (qmr[mf][0] && k1ok) ? S[mf][nf][1] : -FLT_MAX;
                float s2 = (qmr[mf][1] && k0ok) ? S[mf][nf][2] : -FLT_MAX;
                float s3 = (qmr[mf][1] && k1ok) ? S[mf][nf][3] : -FLT_MAX;
                S[mf][nf][0] = s0; S[mf][nf][1] = s1;
                S[mf][nf][2] = s2; S[mf][nf][3] = s3;
                tmax[mf][0] = fmaxf(tmax[mf][0], fmaxf(s0, s1));
                tmax[mf][1] = fmaxf(tmax[mf][1], fmaxf(s2, s3));
            }
#pragma unroll
        for (int mf = 0; mf < 2; mf++)
#pragma unroll
            for (int hf = 0; hf < 2; hf++) {
                tmax[mf][hf] = fmaxf(tmax[mf][hf], __shfl_xor_sync(~0u, tmax[mf][hf], 1));
                tmax[mf][hf] = fmaxf(tmax[mf][hf], __shfl_xor_sync(~0u, tmax[mf][hf], 2));
            }
        if ((lane & 3) == 0) {
#pragma unroll
            for (int mf = 0; mf < 2; mf++)
#pragma unroll
                for (int hf = 0; hf < 2; hf++)
                    mx[widn * 128 + wm + mf * 16 + (lane >> 2) + hf * 8] = tmax[mf][hf];
        }
        __syncthreads();

        float alpha[2][2];
#pragma unroll
        for (int mf = 0; mf < 2; mf++)
#pragma unroll
            for (int hf = 0; hf < 2; hf++) {
                float other = mx[(1 - widn) * 128 + wm + mf * 16 + (lane >> 2) + hf * 8];
                float mnew = fmaxf(mrow[mf][hf], fmaxf(tmax[mf][hf], other));
                alpha[mf][hf] = __expf(mrow[mf][hf] - mnew);
                mrow[mf][hf] = mnew;
            }

        float rs[2][2] = {};
#pragma unroll
        for (int mf = 0; mf < 2; mf++)
#pragma unroll
            for (int nf = 0; nf < 8; nf++) {
                float p0 = __expf(S[mf][nf][0] - mrow[mf][0]);
                float p1 = __expf(S[mf][nf][1] - mrow[mf][0]);
                float p2 = __expf(S[mf][nf][2] - mrow[mf][1]);
                float p3 = __expf(S[mf][nf][3] - mrow[mf][1]);
                S[mf][nf][0] = p0; S[mf][nf][1] = p1;
                S[mf][nf][2] = p2; S[mf][nf][3] = p3;
                rs[mf][0] += p0 + p1;
                rs[mf][1] += p2 + p3;
            }
#pragma unroll
        for (int mf = 0; mf < 2; mf++)
#pragma unroll
            for (int hf = 0; hf < 2; hf++) {
                rs[mf][hf] += __shfl_xor_sync(~0u, rs[mf][hf], 1);
                rs[mf][hf] += __shfl_xor_sync(~0u, rs[mf][hf], 2);
                lrow[mf][hf] = lrow[mf][hf] * alpha[mf][hf] + rs[mf][hf];
            }
#pragma unroll
        for (int mf = 0; mf < 2; mf++)
#pragma unroll
            for (int nf = 0; nf < 8; nf++) {
                Oacc[mf][nf][0] *= alpha[mf][0];
                Oacc[mf][nf][1] *= alpha[mf][0];
                Oacc[mf][nf][2] *= alpha[mf][1];
                Oacc[mf][nf][3] *= alpha[mf][1];
            }

        uint32_t PaH[2][4][4], PaL[2][4][4];
#pragma unroll
        for (int mf = 0; mf < 2; mf++)
#pragma unroll
            for (int j = 0; j < 4; j++) {
#pragma unroll
                for (int half = 0; half < 2; half++) {
                    const float* sv = S[mf][2 * j + half];
                    float h0 = bfr(sv[0]), h1 = bfr(sv[1]);
                    float h2 = bfr(sv[2]), h3 = bfr(sv[3]);
                    PaH[mf][j][half * 2 + 0] = packbf(h0, h1);
                    PaH[mf][j][half * 2 + 1] = packbf(h2, h3);
                    PaL[mf][j][half * 2 + 0] = packbf(sv[0] - h0, sv[1] - h1);
                    PaL[mf][j][half * 2 + 1] = packbf(sv[2] - h2, sv[3] - h3);
                }
            }

#pragma unroll
        for (int j = 0; j < 4; j++) {
            uint32_t vH[8][2], vL[8][2];
#pragma unroll
            for (int g = 0; g < 4; g++) {
                int vrow = wnk + j * 16 + ((lane >> 3) & 1) * 8 + (lane & 7);
                uint32_t ad = kst + (uint32_t)(vrow * 144 + g * 32 + (lane >> 4) * 16);
                uint32_t r0, r1, r2, r3;
                ldsm_x4t(r0, r1, r2, r3, ad + APL_VH);
                vH[g * 2 + 0][0] = r0; vH[g * 2 + 0][1] = r1;
                vH[g * 2 + 1][0] = r2; vH[g * 2 + 1][1] = r3;
                ldsm_x4t(r0, r1, r2, r3, ad + APL_VL);
                vL[g * 2 + 0][0] = r0; vL[g * 2 + 0][1] = r1;
                vL[g * 2 + 1][0] = r2; vL[g * 2 + 1][1] = r3;
            }
#pragma unroll
            for (int mf = 0; mf < 2; mf++)
#pragma unroll
                for (int nf = 0; nf < 8; nf++) {
                    mma_bf16(Oacc[mf][nf], PaH[mf][j], vH[nf]);
                    mma_bf16(Oacc[mf][nf], PaH[mf][j], vL[nf]);
                    mma_bf16(Oacc[mf][nf], PaL[mf][j], vH[nf]);
                }
        }
        __syncthreads();
        if (kt + 2 < NTa) { load_kv(kt + 2); CP_COMMIT(); }
    }

    // ---- combine warp pairs, normalize, meanV override, write split planes --
    float* Op = (float*)(smem + ASTG0 + (wid & 3) * 8192);
    float* lp = (float*)(smem + AMX);
    if (widn == 0) {
        if ((lane & 3) == 0) {
#pragma unroll
            for (int mf = 0; mf < 2; mf++)
#pragma unroll
                for (int hf = 0; hf < 2; hf++)
                    lp[wm + mf * 16 + (lane >> 2) + hf * 8] = lrow[mf][hf];
        }
#pragma unroll
        for (int mf = 0; mf < 2; mf++) {
            int r0 = mf * 16 + (lane >> 2);
#pragma unroll
            for (int nf = 0; nf < 8; nf++) {
                int col = nf * 8 + (lane & 3) * 2;
                *(float2*)&Op[r0 * 64 + col] =
                    make_float2(Oacc[mf][nf][0], Oacc[mf][nf][1]);
                *(float2*)&Op[(r0 + 8) * 64 + col] =
                    make_float2(Oacc[mf][nf][2], Oacc[mf][nf][3]);
            }
        }
    }
    __syncthreads();
    if (widn == 1) {
#pragma unroll
        for (int mf = 0; mf < 2; mf++) {
            int r0 = mf * 16 + (lane >> 2);
            float inv0 = 1.0f / (lrow[mf][0] + lp[wm + r0]);
            float inv1 = 1.0f / (lrow[mf][1] + lp[wm + r0 + 8]);
            size_t gr0 = (size_t)(b * QL + q0 + wm + r0) * KP;
            size_t gr1 = gr0 + (size_t)8 * KP;
#pragma unroll
            for (int nf = 0; nf < 8; nf++) {
                int col = nf * 8 + (lane & 3) * 2;
                float2 p0 = *(float2*)&Op[r0 * 64 + col];
                float2 p1 = *(float2*)&Op[(r0 + 8) * 64 + col];
                float o00 = (Oacc[mf][nf][0] + p0.x) * inv0;
                float o01 = (Oacc[mf][nf][1] + p0.y) * inv0;
                float o10 = (Oacc[mf][nf][2] + p1.x) * inv1;
                float o11 = (Oacc[mf][nf][3] + p1.y) * inv1;
                if (!qmr[mf][0]) {   // fully-masked q row -> uniform mean over ALL keys
                    float2 mv = *(const float2*)&meanv[b * DIMX + h * HD + col];
                    o00 = mv.x; o01 = mv.y;
                }
                if (!qmr[mf][1]) {
                    float2 mv = *(const float2*)&meanv[b * DIMX + h * HD + col];
                    o10 = mv.x; o11 = mv.y;
                }
                float h00 = bfr(o00), h01 = bfr(o01), h10 = bfr(o10), h11 = bfr(o11);
                uint32_t HI0 = packbf(h00, h01), LO0 = packbf(o00 - h00, o01 - h01);
                uint32_t HI1 = packbf(h10, h11), LO1 = packbf(o10 - h10, o11 - h11);
                __nv_bfloat16* pr0 = g_o2 + gr0 + h * HD + col;
                __nv_bfloat16* pr1 = g_o2 + gr1 + h * HD + col;
                *(uint32_t*)(pr0) = HI0;
                *(uint32_t*)(pr0 + DIMX) = HI0;
                *(uint32_t*)(pr0 + 2 * DIMX) = LO0;
                *(uint32_t*)(pr1) = HI1;
                *(uint32_t*)(pr1 + DIMX) = HI1;
                *(uint32_t*)(pr1 + 2 * DIMX) = LO1;
            }
        }
    }
}

// ---------------- host side ----------------
extern "C" void kernel_launch(void* const* d_in, const int* in_sizes, int n_in,
                              void* d_out, int out_size) {
    const float* q = nullptr;
    const float* k = nullptr;
    const int* qm = nullptr;
    const int* km = nullptr;
    for (int i = 0; i < 4; i++) {
        int s = in_sizes[i];
        if (s == BS * QL * DIMX)      q  = (const float*)d_in[i];
        else if (s == BS * KL * DIMX) k  = (const float*)d_in[i];
        else if (s == BS * QL)        qm = (const int*)d_in[i];
        else if (s == BS * KL)        km = (const int*)d_in[i];
    }
    const float* Wq = (const float*)d_in[4];
    const float* bq = (const float*)d_in[5];
    const float* Wk = (const float*)d_in[6];
    const float* bk = (const float*)d_in[7];
    const float* Wv = (const float*)d_in[8];
    const float* bv = (const float*)d_in[9];
    const float* Wo = (const float*)d_in[10];
    const float* bo = (const float*)d_in[11];
    float* out = (float*)d_out;

    __nv_bfloat16 *q2, *k2, *o2, *wq2, *wk2, *wv2, *wo2;
    __nv_bfloat16 *Qh, *Ql, *Kh, *Kl, *Vh, *Vl;
    cudaGetSymbolAddress((void**)&q2, g_q2);
    cudaGetSymbolAddress((void**)&k2, g_k2);
    cudaGetSymbolAddress((void**)&o2, g_o2);
    cudaGetSymbolAddress((void**)&wq2, g_Wq2);
    cudaGetSymbolAddress((void**)&wk2, g_Wk2);
    cudaGetSymbolAddress((void**)&wv2, g_Wv2);
    cudaGetSymbolAddress((void**)&wo2, g_Wo2);
    cudaGetSymbolAddress((void**)&Qh, g_Qh);
    cudaGetSymbolAddress((void**)&Ql, g_Ql);
    cudaGetSymbolAddress((void**)&Kh, g_Kh);
    cudaGetSymbolAddress((void**)&Kl, g_Kl);
    cudaGetSymbolAddress((void**)&Vh, g_Vh);
    cudaGetSymbolAddress((void**)&Vl, g_Vl);
    int* cntp;
    float* meanvp;
    cudaGetSymbolAddress((void**)&cntp, g_cnt);
    cudaGetSymbolAddress((void**)&meanvp, g_meanv);

    cudaFuncSetAttribute(gemm_mma, cudaFuncAttributeMaxDynamicSharedMemorySize,
                         GSTG * 20480);
    cudaFuncSetAttribute(attn_tc, cudaFuncAttributeMaxDynamicSharedMemorySize,
                         ATT_SMEM);

    // ---- compaction metadata + meanV (for fully-masked q rows) ----
    compact_scan<<<BS, 1024>>>(km);
    colmean<<<dim3(DIMX / 256, BS), 256>>>(k);
    meanv_gemv<<<dim3(DIMX / 8, BS), 256>>>(Wv, bv);

    // ---- pack weights + activations ----
    pack_b<<<DIMX * DIMX / 512, 256>>>(Wq, wq2);
    pack_b<<<DIMX * DIMX / 512, 256>>>(Wk, wk2);
    pack_b<<<DIMX * DIMX / 512, 256>>>(Wv, wv2);
    pack_b<<<DIMX * DIMX / 512, 256>>>(Wo, wo2);
    pack_a<<<BS * QL * DIMX / 512, 256>>>(q, q2);
    gather_pack_k<<<BS * KL * DIMX / 512, 256>>>(k);

    // ---- projections (K/V on compacted rows, CTA-skip past active count) ----
    gemm_mma<<<dim3(DIMX / BN, BS * QL / BM), 256, GSTG * 20480>>>(
        q2, wq2, bq, nullptr, Qh, Ql, 0.125f, nullptr);
    gemm_mma<<<dim3(DIMX / BN, BS * KL / BM), 256, GSTG * 20480>>>(
        k2, wk2, bk, nullptr, Kh, Kl, 1.0f, cntp);
    gemm_mma<<<dim3(DIMX / BN, BS * KL / BM), 256, GSTG * 20480>>>(
        k2, wv2, bv, nullptr, Vh, Vl, 1.0f, cntp);

    // ---- flash attention over active keys only ----
    attn_tc<<<dim3(QL / BQ, NH, BS), 256, ATT_SMEM>>>(qm, cntp, meanvp);

    // ---- output projection -> fp32 out ----
    gemm_mma<<<dim3(DIMX / BN, BS * QL / BM), 256, GSTG * 20480>>>(
        o2, wo2, bo, out, nullptr, nullptr, 1.0f, nullptr);
}

// round 6
// speedup vs baseline: 3.9231x; 1.1213x over previous
#include <cuda_runtime.h>
#include <cuda_bf16.h>
#include <float.h>
#include <stdint.h>

#define DIMX 1024
#define NH 16
#define HD 64
#define QL 1024
#define KL 4096
#define BS 2

#define KP 3072            // packed K' = 3 * 1024 (bf16 split: hh + hl + lh)
#define BM 128
#define BN 128
#define BK 32
#define NKT (KP / BK)      // 96 k-tiles
#define GSTG 4             // gemm pipeline stages

// attention tiling
#define BQ 128
#define BKT 128

// ---------------- scratch (__device__ globals; no allocation) ----------------
__device__ __nv_bfloat16 g_q2[BS * QL * KP];      // COMPACTED q rows
__device__ __nv_bfloat16 g_k2[BS * KL * KP];      // COMPACTED k rows
__device__ __nv_bfloat16 g_o2[BS * QL * KP];      // attn out (compact q rows)
__device__ __nv_bfloat16 g_Wq2[DIMX * KP];
__device__ __nv_bfloat16 g_Wk2[DIMX * KP];
__device__ __nv_bfloat16 g_Wv2[DIMX * KP];
__device__ __nv_bfloat16 g_Wo2[DIMX * KP];

// projection outputs as split-bf16 planes (compact row spaces)
__device__ __nv_bfloat16 g_Qh[BS * QL * DIMX];
__device__ __nv_bfloat16 g_Ql[BS * QL * DIMX];
__device__ __nv_bfloat16 g_Kh[BS * KL * DIMX];
__device__ __nv_bfloat16 g_Kl[BS * KL * DIMX];
__device__ __nv_bfloat16 g_Vh[BS * KL * DIMX];
__device__ __nv_bfloat16 g_Vl[BS * KL * DIMX];

// O-projection result on compact q rows
__device__ float g_Oc[BS * QL * DIMX];

// compaction metadata
__device__ int g_cnt[BS];                 // active k count
__device__ int g_cidx[BS * KL];
__device__ int g_cmask[BS * KL];
__device__ int g_qcnt[BS];                // active q count
__device__ int g_qidx[BS * QL];           // compact -> orig
__device__ int g_qpos[BS * QL];           // orig -> compact
__device__ float g_kmean[BS * DIMX];
__device__ float g_meanv[BS * DIMX];
__device__ float g_meanout[BS * DIMX];

// ---------------- low-level helpers (baseline sm_80-era PTX only) ------------
__device__ __forceinline__ uint32_t smem_u32(const void* p) {
    uint32_t a;
    asm("{ .reg .u64 t; cvta.to.shared.u64 t, %1; cvt.u32.u64 %0, t; }" : "=r"(a) : "l"(p));
    return a;
}
#define CP_ASYNC16(dst, src) \
    asm volatile("cp.async.cg.shared.global [%0], [%1], 16;" :: "r"(dst), "l"(src))
#define CP_COMMIT() asm volatile("cp.async.commit_group;" ::: "memory")
#define CP_WAIT(n)  asm volatile("cp.async.wait_group %0;" :: "n"(n) : "memory")

__device__ __forceinline__ void ldsm_x4(uint32_t& r0, uint32_t& r1, uint32_t& r2,
                                        uint32_t& r3, uint32_t addr) {
    asm volatile("ldmatrix.sync.aligned.m8n8.x4.shared.b16 {%0,%1,%2,%3}, [%4];"
                 : "=r"(r0), "=r"(r1), "=r"(r2), "=r"(r3) : "r"(addr));
}
__device__ __forceinline__ void ldsm_x4t(uint32_t& r0, uint32_t& r1, uint32_t& r2,
                                         uint32_t& r3, uint32_t addr) {
    asm volatile("ldmatrix.sync.aligned.m8n8.x4.trans.shared.b16 {%0,%1,%2,%3}, [%4];"
                 : "=r"(r0), "=r"(r1), "=r"(r2), "=r"(r3) : "r"(addr));
}
__device__ __forceinline__ void mma_bf16(float* c, const uint32_t* a, const uint32_t* b) {
    asm volatile(
        "mma.sync.aligned.m16n8k16.row.col.f32.bf16.bf16.f32 "
        "{%0,%1,%2,%3}, {%4,%5,%6,%7}, {%8,%9}, {%0,%1,%2,%3};"
        : "+f"(c[0]), "+f"(c[1]), "+f"(c[2]), "+f"(c[3])
        : "r"(a[0]), "r"(a[1]), "r"(a[2]), "r"(a[3]), "r"(b[0]), "r"(b[1]));
}
__device__ __forceinline__ uint32_t packbf(float lo, float hi) {
    uint32_t d;
    asm("cvt.rn.bf16x2.f32 %0, %1, %2;" : "=r"(d) : "f"(hi), "f"(lo));
    return d;
}
__device__ __forceinline__ float bfr(float x) {
    return __bfloat162float(__float2bfloat16(x));
}

// ---------------- compaction scans -------------------------------------------
__global__ __launch_bounds__(1024) void compact_scan_k(const int* __restrict__ km) {
    __shared__ int ssum[1024];
    const int b = blockIdx.x;
    const int t = threadIdx.x;
    int v[4], s = 0;
#pragma unroll
    for (int i = 0; i < 4; i++) {
        v[i] = km[b * KL + t * 4 + i] != 0 ? 1 : 0;
        s += v[i];
    }
    ssum[t] = s;
    __syncthreads();
    for (int off = 1; off < 1024; off <<= 1) {
        int x = (t >= off) ? ssum[t - off] : 0;
        __syncthreads();
        ssum[t] += x;
        __syncthreads();
    }
    int pos = ssum[t] - s;
#pragma unroll
    for (int i = 0; i < 4; i++) {
        if (v[i]) { g_cidx[b * KL + pos] = t * 4 + i; pos++; }
    }
    int total = ssum[1023];
    if (t == 0) g_cnt[b] = total;
#pragma unroll
    for (int i = 0; i < 4; i++) {
        int idx = t * 4 + i;
        g_cmask[b * KL + idx] = (idx < total) ? 1 : 0;
    }
}

__global__ __launch_bounds__(256) void compact_scan_q(const int* __restrict__ qm) {
    __shared__ int ssum[256];
    const int b = blockIdx.x;
    const int t = threadIdx.x;
    int v[4], s = 0;
#pragma unroll
    for (int i = 0; i < 4; i++) {
        v[i] = qm[b * QL + t * 4 + i] != 0 ? 1 : 0;
        s += v[i];
    }
    ssum[t] = s;
    __syncthreads();
    for (int off = 1; off < 256; off <<= 1) {
        int x = (t >= off) ? ssum[t - off] : 0;
        __syncthreads();
        ssum[t] += x;
        __syncthreads();
    }
    int pos = ssum[t] - s;
#pragma unroll
    for (int i = 0; i < 4; i++) {
        int idx = t * 4 + i;
        if (v[i]) { g_qidx[b * QL + pos] = idx; g_qpos[b * QL + idx] = pos; pos++; }
        else g_qpos[b * QL + idx] = 0;
    }
    if (t == 0) g_qcnt[b] = ssum[255];
}

// column mean of raw k over all KL rows
__global__ __launch_bounds__(256) void colmean(const float* __restrict__ k) {
    const int j = blockIdx.x * 256 + threadIdx.x;
    const int b = blockIdx.y;
    const float* p = k + (size_t)b * KL * DIMX + j;
    float s0 = 0, s1 = 0, s2 = 0, s3 = 0;
    for (int kk = 0; kk < KL; kk += 4) {
        s0 += p[(size_t)kk * DIMX];
        s1 += p[(size_t)(kk + 1) * DIMX];
        s2 += p[(size_t)(kk + 2) * DIMX];
        s3 += p[(size_t)(kk + 3) * DIMX];
    }
    g_kmean[b * DIMX + j] = (s0 + s1 + s2 + s3) * (1.0f / KL);
}

// y[b][d] = x[b] . W[d] + bias[d]   (warp per output row)
__global__ __launch_bounds__(256) void gemv_rowT(const float* __restrict__ W,
                                                 const float* __restrict__ bias,
                                                 const float* __restrict__ x,
                                                 float* __restrict__ y) {
    const int b = blockIdx.y;
    const int lane = threadIdx.x & 31;
    const int d = blockIdx.x * 8 + (threadIdx.x >> 5);
    const float* w = W + (size_t)d * DIMX;
    const float* m = x + b * DIMX;
    float s = 0;
    for (int j = lane; j < DIMX; j += 32) s += m[j] * w[j];
#pragma unroll
    for (int off = 16; off > 0; off >>= 1) s += __shfl_xor_sync(~0u, s, off);
    if (lane == 0) y[b * DIMX + d] = s + bias[d];
}

// ---------------- fp32 -> packed split-bf16 kernels ----------------
__global__ __launch_bounds__(256) void gather_pack_q(const float* __restrict__ q) {
    int idx = blockIdx.x * 256 + threadIdx.x;
    int m = idx >> 9;              // compact row (global, 0..BS*QL)
    int j = (idx & 511) * 2;
    int b = m >> 10;               // QL = 1024
    int i = m & (QL - 1);
    float2 v = {0.0f, 0.0f};
    if (i < g_qcnt[b]) {
        int src = g_qidx[b * QL + i];
        v = *reinterpret_cast<const float2*>(q + ((size_t)(b * QL + src)) * DIMX + j);
    }
    __nv_bfloat16 h0 = __float2bfloat16(v.x), h1 = __float2bfloat16(v.y);
    __nv_bfloat16 l0 = __float2bfloat16(v.x - __bfloat162float(h0));
    __nv_bfloat16 l1 = __float2bfloat16(v.y - __bfloat162float(h1));
    __nv_bfloat162 h; h.x = h0; h.y = h1;
    __nv_bfloat162 l; l.x = l0; l.y = l1;
    size_t base = (size_t)m * KP;
    *reinterpret_cast<__nv_bfloat162*>(g_q2 + base + j) = h;
    *reinterpret_cast<__nv_bfloat162*>(g_q2 + base + DIMX + j) = h;
    *reinterpret_cast<__nv_bfloat162*>(g_q2 + base + 2 * DIMX + j) = l;
}
__global__ __launch_bounds__(256) void gather_pack_k(const float* __restrict__ k) {
    int idx = blockIdx.x * 256 + threadIdx.x;
    int m = idx >> 9;
    int j = (idx & 511) * 2;
    int b = m >> 12;               // KL = 4096
    int i = m & (KL - 1);
    float2 v = {0.0f, 0.0f};
    if (i < g_cnt[b]) {
        int src = g_cidx[b * KL + i];
        v = *reinterpret_cast<const float2*>(k + ((size_t)(b * KL + src)) * DIMX + j);
    }
    __nv_bfloat16 h0 = __float2bfloat16(v.x), h1 = __float2bfloat16(v.y);
    __nv_bfloat16 l0 = __float2bfloat16(v.x - __bfloat162float(h0));
    __nv_bfloat16 l1 = __float2bfloat16(v.y - __bfloat162float(h1));
    __nv_bfloat162 h; h.x = h0; h.y = h1;
    __nv_bfloat162 l; l.x = l0; l.y = l1;
    size_t base = (size_t)m * KP;
    *reinterpret_cast<__nv_bfloat162*>(g_k2 + base + j) = h;
    *reinterpret_cast<__nv_bfloat162*>(g_k2 + base + DIMX + j) = h;
    *reinterpret_cast<__nv_bfloat162*>(g_k2 + base + 2 * DIMX + j) = l;
}
__global__ __launch_bounds__(256) void pack_b(const float* __restrict__ x,
                                              __nv_bfloat16* __restrict__ y) {
    int idx = blockIdx.x * 256 + threadIdx.x;
    int m = idx >> 9;
    int j = (idx & 511) * 2;
    float2 v = *reinterpret_cast<const float2*>(x + (size_t)m * DIMX + j);
    __nv_bfloat16 h0 = __float2bfloat16(v.x), h1 = __float2bfloat16(v.y);
    __nv_bfloat16 l0 = __float2bfloat16(v.x - __bfloat162float(h0));
    __nv_bfloat16 l1 = __float2bfloat16(v.y - __bfloat162float(h1));
    __nv_bfloat162 h; h.x = h0; h.y = h1;
    __nv_bfloat162 l; l.x = l0; l.y = l1;
    size_t base = (size_t)m * KP;
    *reinterpret_cast<__nv_bfloat162*>(y + base + j) = h;
    *reinterpret_cast<__nv_bfloat162*>(y + base + DIMX + j) = l;
    *reinterpret_cast<__nv_bfloat162*>(y + base + 2 * DIMX + j) = h;
}

// ---------------- warp-MMA GEMM (4-stage cp.async pipeline) ------------------
// cnt != nullptr => rows per-batch compacted (2^bshift row space); skip CTAs
// beyond the 128-padded active count.
__global__ __launch_bounds__(256) void gemm_mma(const __nv_bfloat16* __restrict__ A,
                                                const __nv_bfloat16* __restrict__ B,
                                                const float* __restrict__ bias,
                                                float* __restrict__ Cf,
                                                __nv_bfloat16* __restrict__ Ph,
                                                __nv_bfloat16* __restrict__ Pl,
                                                float scale,
                                                const int* __restrict__ cnt,
                                                int bshift) {
    extern __shared__ __align__(16) char smem_g[];
    const uint32_t sbase = smem_u32(smem_g);
    const int tid = threadIdx.x;
    const int lane = tid & 31;
    const int wid = tid >> 5;
    const int wm = (wid & 3) * 32;
    const int wn = (wid >> 2) * 64;
    const int n0 = blockIdx.x * BN, m0 = blockIdx.y * BM;

    if (cnt) {
        int b = m0 >> bshift;
        int local = m0 & ((1 << bshift) - 1);
        int padded = (cnt[b] + 127) & ~127;
        if (local >= padded) return;
    }

    const __nv_bfloat16* Abase = A + (size_t)m0 * KP;
    const __nv_bfloat16* Bbase = B + (size_t)n0 * KP;

    const int r0_ = tid >> 2, r1_ = (tid + 256) >> 2;
    const int s0_ = (tid & 3) * 8;
    const uint32_t soffA0 = (uint32_t)(r0_ * 80 + (tid & 3) * 16);
    const uint32_t soffA1 = (uint32_t)(r1_ * 80 + (tid & 3) * 16);

    float acc[2][8][4] = {};

    auto load_stage = [&](int kt, int s) {
        uint32_t sa = sbase + (uint32_t)s * 20480u;
        uint32_t sb = sa + 10240u;
        const __nv_bfloat16* Ak = Abase + kt * BK;
        const __nv_bfloat16* Bk = Bbase + kt * BK;
        CP_ASYNC16(sa + soffA0, Ak + (size_t)r0_ * KP + s0_);
        CP_ASYNC16(sa + soffA1, Ak + (size_t)r1_ * KP + s0_);
        CP_ASYNC16(sb + soffA0, Bk + (size_t)r0_ * KP + s0_);
        CP_ASYNC16(sb + soffA1, Bk + (size_t)r1_ * KP + s0_);
        CP_COMMIT();
    };

    load_stage(0, 0);
    load_stage(1, 1);
    load_stage(2, 2);

    for (int kt = 0; kt < NKT; kt++) {
        if (kt < NKT - 2) { CP_WAIT(2); }
        else if (kt == NKT - 2) { CP_WAIT(1); }
        else { CP_WAIT(0); }
        __syncthreads();
        if (kt + 3 < NKT) load_stage(kt + 3, (kt + 3) & 3);

        uint32_t sa = sbase + (uint32_t)(kt & 3) * 20480u;
        uint32_t sb = sa + 10240u;
#pragma unroll
        for (int s = 0; s < 2; s++) {
            uint32_t aF[2][4], bF[8][2];
#pragma unroll
            for (int mf = 0; mf < 2; mf++) {
                uint32_t addr = sa + (uint32_t)((wm + mf * 16 + (lane & 15)) * 80 +
                                                s * 32 + (lane >> 4) * 16);
                ldsm_x4(aF[mf][0], aF[mf][1], aF[mf][2], aF[mf][3], addr);
            }
#pragma unroll
            for (int nf4 = 0; nf4 < 4; nf4++) {
                int nrow = wn + nf4 * 16 + ((lane >> 4) * 8) + (lane & 7);
                uint32_t addr = sb + (uint32_t)(nrow * 80 + s * 32 +
                                                (((lane >> 3) & 1) * 16));
                uint32_t q0, q1, q2, q3;
                ldsm_x4(q0, q1, q2, q3, addr);
                bF[nf4 * 2 + 0][0] = q0; bF[nf4 * 2 + 0][1] = q1;
                bF[nf4 * 2 + 1][0] = q2; bF[nf4 * 2 + 1][1] = q3;
            }
#pragma unroll
            for (int mf = 0; mf < 2; mf++)
#pragma unroll
                for (int nf = 0; nf < 8; nf++)
                    mma_bf16(acc[mf][nf], aF[mf], bF[nf]);
        }
    }

#pragma unroll
    for (int mf = 0; mf < 2; mf++) {
        int rbase = m0 + wm + mf * 16 + (lane >> 2);
#pragma unroll
        for (int nf = 0; nf < 8; nf++) {
            int col = n0 + wn + nf * 8 + (lane & 3) * 2;
            float2 bv = *reinterpret_cast<const float2*>(bias + col);
            float v00 = (acc[mf][nf][0] + bv.x) * scale;
            float v01 = (acc[mf][nf][1] + bv.y) * scale;
            float v10 = (acc[mf][nf][2] + bv.x) * scale;
            float v11 = (acc[mf][nf][3] + bv.y) * scale;
            if (Ph) {
                float h00 = bfr(v00), h01 = bfr(v01), h10 = bfr(v10), h11 = bfr(v11);
                size_t o0 = (size_t)rbase * DIMX + col;
                size_t o1 = (size_t)(rbase + 8) * DIMX + col;
                *reinterpret_cast<uint32_t*>(Ph + o0) = packbf(h00, h01);
                *reinterpret_cast<uint32_t*>(Pl + o0) = packbf(v00 - h00, v01 - h01);
                *reinterpret_cast<uint32_t*>(Ph + o1) = packbf(h10, h11);
                *reinterpret_cast<uint32_t*>(Pl + o1) = packbf(v10 - h10, v11 - h11);
            } else {
                float2 o0 = {v00, v01}, o1 = {v10, v11};
                *reinterpret_cast<float2*>(Cf + (size_t)rbase * DIMX + col) = o0;
                *reinterpret_cast<float2*>(Cf + (size_t)(rbase + 8) * DIMX + col) = o1;
            }
        }
    }
}

// ---------------- tensor-core flash attention (both sides compacted) ---------
#define AQH 0
#define AQL 18432
#define ASTG0 36864
#define STGB 73728
#define APL_KH 0
#define APL_KL 18432
#define APL_VH 36864
#define APL_VL 55296
#define AMX  184320
#define AKM0 185344
#define ATT_SMEM (185344 + 1024)

__global__ __launch_bounds__(256, 1) void attn_tc(const int* __restrict__ cnt,
                                                  const int* __restrict__ qcnt) {
    extern __shared__ __align__(16) char smem[];
    const uint32_t sb = smem_u32(smem);
    const int tid = threadIdx.x;
    const int lane = tid & 31;
    const int wid = tid >> 5;
    const int wm = (wid & 3) * 32;
    const int widn = wid >> 2;
    const int wnk = widn * 64;
    const int q0 = blockIdx.x * BQ;
    const int h = blockIdx.y;
    const int b = blockIdx.z;

    // skip tiles past the active (padded) q count
    if (q0 >= ((qcnt[b] + 127) & ~127)) return;

    const int NTa = (cnt[b] + BKT - 1) >> 7;   // active k-tiles

    auto load_kv = [&](int kt2) {
        int s = kt2 & 1;
        int k0 = kt2 * BKT;
        uint32_t dstb = sb + ASTG0 + (uint32_t)s * STGB;
        size_t rowbase = (size_t)(b * KL + k0);
#pragma unroll
        for (int p = 0; p < 4; p++) {
            const __nv_bfloat16* sp = (p == 0) ? g_Kh : (p == 1) ? g_Kl
                                     : (p == 2) ? g_Vh : g_Vl;
            uint32_t dp = dstb + (uint32_t)p * 18432u;
#pragma unroll
            for (int i = 0; i < 4; i++) {
                int c = tid + i * 256;
                int row = c >> 3, ch = c & 7;
                CP_ASYNC16(dp + (uint32_t)(row * 144 + ch * 16),
                           sp + (((rowbase + row) << 10) + h * HD + ch * 8));
            }
        }
        if (tid < 32)
            CP_ASYNC16(sb + AKM0 + (uint32_t)(s * 512 + tid * 16),
                       g_cmask + b * KL + k0 + tid * 4);
    };

    {
        size_t rowbase = (size_t)(b * QL + q0);
#pragma unroll
        for (int p = 0; p < 2; p++) {
            const __nv_bfloat16* sp = p == 0 ? g_Qh : g_Ql;
            uint32_t dp = sb + (uint32_t)(p * 18432);
#pragma unroll
            for (int i = 0; i < 4; i++) {
                int c = tid + i * 256;
                int row = c >> 3, ch = c & 7;
                CP_ASYNC16(dp + (uint32_t)(row * 144 + ch * 16),
                           sp + (((rowbase + row) << 10) + h * HD + ch * 8));
            }
        }
        load_kv(0);
        CP_COMMIT();
        load_kv(1 < NTa ? 1 : 0);
        CP_COMMIT();
    }

    float mrow[2][2], lrow[2][2], Oacc[2][8][4] = {};
#pragma unroll
    for (int mf = 0; mf < 2; mf++)
#pragma unroll
        for (int hf = 0; hf < 2; hf++) { mrow[mf][hf] = -FLT_MAX; lrow[mf][hf] = 0.0f; }

    float* mx = (float*)(smem + AMX);

    for (int kt = 0; kt < NTa; kt++) {
        if (kt < NTa - 1) { CP_WAIT(1); } else { CP_WAIT(0); }
        __syncthreads();
        const uint32_t kst = sb + ASTG0 + (uint32_t)(kt & 1) * STGB;
        const int* kms = (const int*)(smem + AKM0 + (kt & 1) * 512);

        int2 kmv[8];
#pragma unroll
        for (int nf = 0; nf < 8; nf++)
            kmv[nf] = *(const int2*)&kms[wnk + nf * 8 + (lane & 3) * 2];

        float S[2][8][4] = {};
#pragma unroll
        for (int s16 = 0; s16 < 4; s16++) {
            uint32_t aH[2][4], aL[2][4];
#pragma unroll
            for (int mf = 0; mf < 2; mf++) {
                uint32_t ad = sb + (uint32_t)((wm + mf * 16 + (lane & 15)) * 144 +
                                              s16 * 32 + (lane >> 4) * 16);
                ldsm_x4(aH[mf][0], aH[mf][1], aH[mf][2], aH[mf][3], ad);
                ldsm_x4(aL[mf][0], aL[mf][1], aL[mf][2], aL[mf][3], ad + 18432u);
            }
            uint32_t bH[8][2], bL[8][2];
#pragma unroll
            for (int nf4 = 0; nf4 < 4; nf4++) {
                int nrow = wnk + nf4 * 16 + ((lane >> 4) * 8) + (lane & 7);
                uint32_t ad = kst + (uint32_t)(nrow * 144 + s16 * 32 +
                                               (((lane >> 3) & 1) * 16));
                uint32_t r0, r1, r2, r3;
                ldsm_x4(r0, r1, r2, r3, ad + APL_KH);
                bH[nf4 * 2 + 0][0] = r0; bH[nf4 * 2 + 0][1] = r1;
                bH[nf4 * 2 + 1][0] = r2; bH[nf4 * 2 + 1][1] = r3;
                ldsm_x4(r0, r1, r2, r3, ad + APL_KL);
                bL[nf4 * 2 + 0][0] = r0; bL[nf4 * 2 + 0][1] = r1;
                bL[nf4 * 2 + 1][0] = r2; bL[nf4 * 2 + 1][1] = r3;
            }
#pragma unroll
            for (int mf = 0; mf < 2; mf++)
#pragma unroll
                for (int nf = 0; nf < 8; nf++) {
                    mma_bf16(S[mf][nf], aH[mf], bH[nf]);
                    mma_bf16(S[mf][nf], aH[mf], bL[nf]);
                    mma_bf16(S[mf][nf], aL[mf], bH[nf]);
                }
        }

        // ---- mask pad keys + partial row max ----
        float tmax[2][2] = {{-FLT_MAX, -FLT_MAX}, {-FLT_MAX, -FLT_MAX}};
#pragma unroll
        for (int mf = 0; mf < 2; mf++)
#pragma unroll
            for (int nf = 0; nf < 8; nf++) {
                bool k0ok = kmv[nf].x != 0, k1ok = kmv[nf].y != 0;
                float s0 = k0ok ? S[mf][nf][0] : -FLT_MAX;
                float s1 = k1ok ? S[mf][nf][1] : -FLT_MAX;
                float s2 = k0ok ? S[mf][nf][2] : -FLT_MAX;
                float s3 = k1ok ? S[mf][nf][3] : -FLT_MAX;
                S[mf][nf][0] = s0; S[mf][nf][1] = s1;
                S[mf][nf][2] = s2; S[mf][nf][3] = s3;
                tmax[mf][0] = fmaxf(tmax[mf][0], fmaxf(s0, s1));
                tmax[mf][1] = fmaxf(tmax[mf][1], fmaxf(s2, s3));
            }
#pragma unroll
        for (int mf = 0; mf < 2; mf++)
#pragma unroll
            for (int hf = 0; hf < 2; hf++) {
                tmax[mf][hf] = fmaxf(tmax[mf][hf], __shfl_xor_sync(~0u, tmax[mf][hf], 1));
                tmax[mf][hf] = fmaxf(tmax[mf][hf], __shfl_xor_sync(~0u, tmax[mf][hf], 2));
            }
        if ((lane & 3) == 0) {
#pragma unroll
            for (int mf = 0; mf < 2; mf++)
#pragma unroll
                for (int hf = 0; hf < 2; hf++)
                    mx[widn * 128 + wm + mf * 16 + (lane >> 2) + hf * 8] = tmax[mf][hf];
        }
        __syncthreads();

        float alpha[2][2];
#pragma unroll
        for (int mf = 0; mf < 2; mf++)
#pragma unroll
            for (int hf = 0; hf < 2; hf++) {
                float other = mx[(1 - widn) * 128 + wm + mf * 16 + (lane >> 2) + hf * 8];
                float mnew = fmaxf(mrow[mf][hf], fmaxf(tmax[mf][hf], other));
                alpha[mf][hf] = __expf(mrow[mf][hf] - mnew);
                mrow[mf][hf] = mnew;
            }

        float rs[2][2] = {};
#pragma unroll
        for (int mf = 0; mf < 2; mf++)
#pragma unroll
            for (int nf = 0; nf < 8; nf++) {
                float p0 = __expf(S[mf][nf][0] - mrow[mf][0]);
                float p1 = __expf(S[mf][nf][1] - mrow[mf][0]);
                float p2 = __expf(S[mf][nf][2] - mrow[mf][1]);
                float p3 = __expf(S[mf][nf][3] - mrow[mf][1]);
                S[mf][nf][0] = p0; S[mf][nf][1] = p1;
                S[mf][nf][2] = p2; S[mf][nf][3] = p3;
                rs[mf][0] += p0 + p1;
                rs[mf][1] += p2 + p3;
            }
#pragma unroll
        for (int mf = 0; mf < 2; mf++)
#pragma unroll
            for (int hf = 0; hf < 2; hf++) {
                rs[mf][hf] += __shfl_xor_sync(~0u, rs[mf][hf], 1);
                rs[mf][hf] += __shfl_xor_sync(~0u, rs[mf][hf], 2);
                lrow[mf][hf] = lrow[mf][hf] * alpha[mf][hf] + rs[mf][hf];
            }
#pragma unroll
        for (int mf = 0; mf < 2; mf++)
#pragma unroll
            for (int nf = 0; nf < 8; nf++) {
                Oacc[mf][nf][0] *= alpha[mf][0];
                Oacc[mf][nf][1] *= alpha[mf][0];
                Oacc[mf][nf][2] *= alpha[mf][1];
                Oacc[mf][nf][3] *= alpha[mf][1];
            }

        uint32_t PaH[2][4][4], PaL[2][4][4];
#pragma unroll
        for (int mf = 0; mf < 2; mf++)
#pragma unroll
            for (int j = 0; j < 4; j++) {
#pragma unroll
                for (int half = 0; half < 2; half++) {
                    const float* sv = S[mf][2 * j + half];
                    float h0 = bfr(sv[0]), h1 = bfr(sv[1]);
                    float h2 = bfr(sv[2]), h3 = bfr(sv[3]);
                    PaH[mf][j][half * 2 + 0] = packbf(h0, h1);
                    PaH[mf][j][half * 2 + 1] = packbf(h2, h3);
                    PaL[mf][j][half * 2 + 0] = packbf(sv[0] - h0, sv[1] - h1);
                    PaL[mf][j][half * 2 + 1] = packbf(sv[2] - h2, sv[3] - h3);
                }
            }

#pragma unroll
        for (int j = 0; j < 4; j++) {
            uint32_t vH[8][2], vL[8][2];
#pragma unroll
            for (int g = 0; g < 4; g++) {
                int vrow = wnk + j * 16 + ((lane >> 3) & 1) * 8 + (lane & 7);
                uint32_t ad = kst + (uint32_t)(vrow * 144 + g * 32 + (lane >> 4) * 16);
                uint32_t r0, r1, r2, r3;
                ldsm_x4t(r0, r1, r2, r3, ad + APL_VH);
                vH[g * 2 + 0][0] = r0; vH[g * 2 + 0][1] = r1;
                vH[g * 2 + 1][0] = r2; vH[g * 2 + 1][1] = r3;
                ldsm_x4t(r0, r1, r2, r3, ad + APL_VL);
                vL[g * 2 + 0][0] = r0; vL[g * 2 + 0][1] = r1;
                vL[g * 2 + 1][0] = r2; vL[g * 2 + 1][1] = r3;
            }
#pragma unroll
            for (int mf = 0; mf < 2; mf++)
#pragma unroll
                for (int nf = 0; nf < 8; nf++) {
                    mma_bf16(Oacc[mf][nf], PaH[mf][j], vH[nf]);
                    mma_bf16(Oacc[mf][nf], PaH[mf][j], vL[nf]);
                    mma_bf16(Oacc[mf][nf], PaL[mf][j], vH[nf]);
                }
        }
        __syncthreads();
        if (kt + 2 < NTa) { load_kv(kt + 2); CP_COMMIT(); }
    }

    // ---- combine warp pairs, normalize, write split planes to g_o2 ----------
    float* Op = (float*)(smem + ASTG0 + (wid & 3) * 8192);
    float* lp = (float*)(smem + AMX);
    if (widn == 0) {
        if ((lane & 3) == 0) {
#pragma unroll
            for (int mf = 0; mf < 2; mf++)
#pragma unroll
                for (int hf = 0; hf < 2; hf++)
                    lp[wm + mf * 16 + (lane >> 2) + hf * 8] = lrow[mf][hf];
        }
#pragma unroll
        for (int mf = 0; mf < 2; mf++) {
            int r0 = mf * 16 + (lane >> 2);
#pragma unroll
            for (int nf = 0; nf < 8; nf++) {
                int col = nf * 8 + (lane & 3) * 2;
                *(float2*)&Op[r0 * 64 + col] =
                    make_float2(Oacc[mf][nf][0], Oacc[mf][nf][1]);
                *(float2*)&Op[(r0 + 8) * 64 + col] =
                    make_float2(Oacc[mf][nf][2], Oacc[mf][nf][3]);
            }
        }
    }
    __syncthreads();
    if (widn == 1) {
#pragma unroll
        for (int mf = 0; mf < 2; mf++) {
            int r0 = mf * 16 + (lane >> 2);
            float inv0 = 1.0f / (lrow[mf][0] + lp[wm + r0]);
            float inv1 = 1.0f / (lrow[mf][1] + lp[wm + r0 + 8]);
            size_t gr0 = (size_t)(b * QL + q0 + wm + r0) * KP;
            size_t gr1 = gr0 + (size_t)8 * KP;
#pragma unroll
            for (int nf = 0; nf < 8; nf++) {
                int col = nf * 8 + (lane & 3) * 2;
                float2 p0 = *(float2*)&Op[r0 * 64 + col];
                float2 p1 = *(float2*)&Op[(r0 + 8) * 64 + col];
                float o00 = (Oacc[mf][nf][0] + p0.x) * inv0;
                float o01 = (Oacc[mf][nf][1] + p0.y) * inv0;
                float o10 = (Oacc[mf][nf][2] + p1.x) * inv1;
                float o11 = (Oacc[mf][nf][3] + p1.y) * inv1;
                float h00 = bfr(o00), h01 = bfr(o01), h10 = bfr(o10), h11 = bfr(o11);
                uint32_t HI0 = packbf(h00, h01), LO0 = packbf(o00 - h00, o01 - h01);
                uint32_t HI1 = packbf(h10, h11), LO1 = packbf(o10 - h10, o11 - h11);
                __nv_bfloat16* pr0 = g_o2 + gr0 + h * HD + col;
                __nv_bfloat16* pr1 = g_o2 + gr1 + h * HD + col;
                *(uint32_t*)(pr0) = HI0;
                *(uint32_t*)(pr0 + DIMX) = HI0;
                *(uint32_t*)(pr0 + 2 * DIMX) = LO0;
                *(uint32_t*)(pr1) = HI1;
                *(uint32_t*)(pr1 + DIMX) = HI1;
                *(uint32_t*)(pr1 + 2 * DIMX) = LO1;
            }
        }
    }
}

// ---------------- scatter: compact O rows + meanout -> final output ----------
__global__ __launch_bounds__(256) void scatter_out(const int* __restrict__ qm,
                                                   float* __restrict__ out) {
    const int r = blockIdx.x;            // orig row (0..BS*QL)
    const int b = r >> 10;               // QL = 1024
    const float4* src;
    if (qm[r] != 0)
        src = (const float4*)(g_Oc + (size_t)(b * QL + g_qpos[r]) * DIMX);
    else
        src = (const float4*)(g_meanout + b * DIMX);
    ((float4*)(out + (size_t)r * DIMX))[threadIdx.x] = src[threadIdx.x];
}

// ---------------- host side ----------------
extern "C" void kernel_launch(void* const* d_in, const int* in_sizes, int n_in,
                              void* d_out, int out_size) {
    const float* q = nullptr;
    const float* k = nullptr;
    const int* qm = nullptr;
    const int* km = nullptr;
    for (int i = 0; i < 4; i++) {
        int s = in_sizes[i];
        if (s == BS * QL * DIMX)      q  = (const float*)d_in[i];
        else if (s == BS * KL * DIMX) k  = (const float*)d_in[i];
        else if (s == BS * QL)        qm = (const int*)d_in[i];
        else if (s == BS * KL)        km = (const int*)d_in[i];
    }
    const float* Wq = (const float*)d_in[4];
    const float* bq = (const float*)d_in[5];
    const float* Wk = (const float*)d_in[6];
    const float* bk = (const float*)d_in[7];
    const float* Wv = (const float*)d_in[8];
    const float* bv = (const float*)d_in[9];
    const float* Wo = (const float*)d_in[10];
    const float* bo = (const float*)d_in[11];
    float* out = (float*)d_out;

    __nv_bfloat16 *q2, *k2, *o2, *wq2, *wk2, *wv2, *wo2;
    __nv_bfloat16 *Qh, *Ql, *Kh, *Kl, *Vh, *Vl;
    cudaGetSymbolAddress((void**)&q2, g_q2);
    cudaGetSymbolAddress((void**)&k2, g_k2);
    cudaGetSymbolAddress((void**)&o2, g_o2);
    cudaGetSymbolAddress((void**)&wq2, g_Wq2);
    cudaGetSymbolAddress((void**)&wk2, g_Wk2);
    cudaGetSymbolAddress((void**)&wv2, g_Wv2);
    cudaGetSymbolAddress((void**)&wo2, g_Wo2);
    cudaGetSymbolAddress((void**)&Qh, g_Qh);
    cudaGetSymbolAddress((void**)&Ql, g_Ql);
    cudaGetSymbolAddress((void**)&Kh, g_Kh);
    cudaGetSymbolAddress((void**)&Kl, g_Kl);
    cudaGetSymbolAddress((void**)&Vh, g_Vh);
    cudaGetSymbolAddress((void**)&Vl, g_Vl);
    int *cntp, *qcntp;
    float *meanvp, *meanoutp, *kmeanp, *Ocp;
    cudaGetSymbolAddress((void**)&cntp, g_cnt);
    cudaGetSymbolAddress((void**)&qcntp, g_qcnt);
    cudaGetSymbolAddress((void**)&meanvp, g_meanv);
    cudaGetSymbolAddress((void**)&meanoutp, g_meanout);
    cudaGetSymbolAddress((void**)&kmeanp, g_kmean);
    cudaGetSymbolAddress((void**)&Ocp, g_Oc);

    cudaFuncSetAttribute(gemm_mma, cudaFuncAttributeMaxDynamicSharedMemorySize,
                         GSTG * 20480);
    cudaFuncSetAttribute(attn_tc, cudaFuncAttributeMaxDynamicSharedMemorySize,
                         ATT_SMEM);

    // ---- compaction metadata + mean path ----
    compact_scan_k<<<BS, 1024>>>(km);
    compact_scan_q<<<BS, 256>>>(qm);
    colmean<<<dim3(DIMX / 256, BS), 256>>>(k);
    gemv_rowT<<<dim3(DIMX / 8, BS), 256>>>(Wv, bv, kmeanp, meanvp);
    gemv_rowT<<<dim3(DIMX / 8, BS), 256>>>(Wo, bo, meanvp, meanoutp);

    // ---- pack weights + gather/pack activations ----
    pack_b<<<DIMX * DIMX / 512, 256>>>(Wq, wq2);
    pack_b<<<DIMX * DIMX / 512, 256>>>(Wk, wk2);
    pack_b<<<DIMX * DIMX / 512, 256>>>(Wv, wv2);
    pack_b<<<DIMX * DIMX / 512, 256>>>(Wo, wo2);
    gather_pack_q<<<BS * QL * DIMX / 512, 256>>>(q);
    gather_pack_k<<<BS * KL * DIMX / 512, 256>>>(k);

    // ---- projections on compacted rows (CTA skip past active counts) ----
    gemm_mma<<<dim3(DIMX / BN, BS * QL / BM), 256, GSTG * 20480>>>(
        q2, wq2, bq, nullptr, Qh, Ql, 0.125f, qcntp, 10);
    gemm_mma<<<dim3(DIMX / BN, BS * KL / BM), 256, GSTG * 20480>>>(
        k2, wk2, bk, nullptr, Kh, Kl, 1.0f, cntp, 12);
    gemm_mma<<<dim3(DIMX / BN, BS * KL / BM), 256, GSTG * 20480>>>(
        k2, wv2, bv, nullptr, Vh, Vl, 1.0f, cntp, 12);

    // ---- flash attention: active q x active k only ----
    attn_tc<<<dim3(QL / BQ, NH, BS), 256, ATT_SMEM>>>(cntp, qcntp);

    // ---- output projection on compact q rows ----
    gemm_mma<<<dim3(DIMX / BN, BS * QL / BM), 256, GSTG * 20480>>>(
        o2, wo2, bo, Ocp, nullptr, nullptr, 1.0f, qcntp, 10);

    // ---- scatter: active rows from Oc, masked rows from meanout ----
    scatter_out<<<BS * QL, 256>>>(qm, out);
}